// round 10
// baseline (speedup 1.0000x reference)
#include <cuda_runtime.h>
#include <cuda_bf16.h>
#include <math.h>
#include <stdint.h>

namespace fa {

constexpr int N4 = 4096, D = 64, J = 256, BH = 32, SPLIT = 16;
constexpr size_t NT = (size_t)BH * N4;          // 131072 rows

constexpr float DATA_NORM = 0.35355339059327373f;
constexpr float RATIO     = 0.0625f;
constexpr float DIAG_C    = 0.0625f;
constexpr float KEPS      = 1e-4f;

// ---- scratch ----
__device__ uint32_t g_Ph[J * 32], g_Pl[J * 32];
__device__ __align__(16) uint32_t g_qp_h[NT * 128];   // qp, A-fragment-tiled
__device__ __align__(16) uint32_t g_qp_l[NT * 128];
__device__ __align__(16) uint32_t g_ET_h[(size_t)BH * 16 * 256 * 128]; // E^T tiles
__device__ __align__(16) uint32_t g_ET_l[(size_t)BH * 16 * 256 * 128];
__device__ __align__(16) uint32_t g_vt_h[(size_t)BH * 72 * 2048];      // v^T (+ones)
__device__ __align__(16) uint32_t g_vt_l[(size_t)BH * 72 * 2048];
__device__ float    g_vsump[BH * 32 * 64];
__device__ float    g_ctxp[(size_t)BH * SPLIT * 256 * 72];
__device__ __align__(16) uint32_t g_bout_h[BH * 72 * 128];
__device__ __align__(16) uint32_t g_bout_l[BH * 72 * 128];
__device__ unsigned g_kmax_u;

__device__ __forceinline__ unsigned fenc(float f) {
    unsigned u = __float_as_uint(f);
    return (u & 0x80000000u) ? ~u : (u | 0x80000000u);
}
__device__ __forceinline__ float fdec(unsigned u) {
    unsigned b = (u & 0x80000000u) ? (u & 0x7fffffffu) : ~u;
    return __uint_as_float(b);
}
__device__ __forceinline__ uint32_t bpack(float a, float b) {
    uint32_t r;
    asm("cvt.rn.bf16x2.f32 %0, %1, %2;" : "=r"(r) : "f"(b), "f"(a));
    return r;
}
__device__ __forceinline__ void split2(float a, float b, uint32_t& hi, uint32_t& lo) {
    hi = bpack(a, b);
    float ha = __uint_as_float(hi << 16);
    float hb = __uint_as_float(hi & 0xffff0000u);
    lo = bpack(a - ha, b - hb);
}
// fp32 exp via FMA-pipe poly (rel err ~1.7e-7)
__device__ __forceinline__ float fexp(float x) {
    float t = x * 1.4426950408889634f;
    float r = rintf(t);
    float f = t - r;
    float p = 1.53989857e-4f;
    p = fmaf(p, f, 1.33335581e-3f);
    p = fmaf(p, f, 9.61812910e-3f);
    p = fmaf(p, f, 5.55041087e-2f);
    p = fmaf(p, f, 2.40226507e-1f);
    p = fmaf(p, f, 6.93147181e-1f);
    p = fmaf(p, f, 1.0f);
    int ei = (int)r;
    ei = ei < -126 ? -126 : (ei > 127 ? 127 : ei);
    return p * __int_as_float((ei + 127) << 23);
}
__device__ __forceinline__ void mma16(float* c, const uint32_t* a, const uint32_t* b) {
    asm volatile(
        "mma.sync.aligned.m16n8k16.row.col.f32.bf16.bf16.f32 "
        "{%0,%1,%2,%3}, {%4,%5,%6,%7}, {%8,%9}, {%0,%1,%2,%3};"
        : "+f"(c[0]), "+f"(c[1]), "+f"(c[2]), "+f"(c[3])
        : "r"(a[0]), "r"(a[1]), "r"(a[2]), "r"(a[3]), "r"(b[0]), "r"(b[1]));
}
__device__ __forceinline__ uint32_t smem_u32(const void* p) {
    uint32_t a;
    asm("{ .reg .u64 t; cvta.to.shared.u64 t, %1; cvt.u32.u64 %0, t; }" : "=r"(a) : "l"(p));
    return a;
}
__device__ __forceinline__ void cpa16(uint32_t saddr, const void* gptr) {
    asm volatile("cp.async.cg.shared.global [%0], [%1], 16;" :: "r"(saddr), "l"(gptr));
}
__device__ __forceinline__ void cpa_commit() {
    asm volatile("cp.async.commit_group;" ::: "memory");
}
__device__ __forceinline__ void cpa_wait0() {
    asm volatile("cp.async.wait_group 0;" ::: "memory");
}

// ===========================================================================
// Prep P + init max.  <<<1,256>>>
// ===========================================================================
__global__ void k_prep_P(const float* __restrict__ P)
{
    const int j = threadIdx.x;
    if (j == 0) g_kmax_u = 0x007FFFFFu;
#pragma unroll
    for (int c = 0; c < 32; c++) {
        uint32_t hi, lo;
        split2(P[j * 64 + 2 * c], P[j * 64 + 2 * c + 1], hi, lo);
        g_Ph[j * 32 + c] = hi;
        g_Pl[j * 32 + c] = lo;
    }
}

// ===========================================================================
// Prep v: v^T split bf16 [bh][72][2048 w] (row64=ones, 65..71=0) + vsum
// partials. grid (32 bh, 32 chunks of 128 n), 256 thr. Coalesced stores.
// ===========================================================================
__global__ void __launch_bounds__(256) k_prep_v(const float* __restrict__ v)
{
    __shared__ float vsm[128 * 65];
    const int bh = blockIdx.x, ch = blockIdx.y, tid = threadIdx.x;
    const size_t base = ((size_t)bh * N4 + (size_t)ch * 128) * D;
    for (int i = tid; i < 128 * 64; i += 256)
        vsm[(i >> 6) * 65 + (i & 63)] = v[base + i];
    __syncthreads();

    if (tid < 64) {
        float s = 0.f;
#pragma unroll 8
        for (int n = 0; n < 128; n++) s += vsm[n * 65 + tid];
        g_vsump[(bh * 32 + ch) * 64 + tid] = s;
    }
    for (int i = tid; i < 72 * 64; i += 256) {
        int e = i >> 6, w = i & 63;
        uint32_t hi, lo;
        if (e < 64) {
            split2(vsm[(2 * w) * 65 + e], vsm[(2 * w + 1) * 65 + e], hi, lo);
        } else if (e == 64) { hi = 0x3F803F80u; lo = 0u; }
        else                { hi = 0u; lo = 0u; }
        size_t dst = ((size_t)(bh * 72 + e)) * 2048 + ch * 64 + w;
        g_vt_h[dst] = hi;
        g_vt_l[dst] = lo;
    }
}

// ===========================================================================
// Projection: 64 rows x 256 j per block; bf16 3-split MMA (R6-identical).
//  IS_Q: qp A-fragment-tiled.  !IS_Q: E^T A-fragment-tiled + atomicMax.
// ===========================================================================
constexpr int KP = 36;
constexpr size_t SMEM_PROJ = (size_t)(2 * J * KP + 2 * 64 * KP) * sizeof(uint32_t);

template <bool IS_Q>
__global__ void __launch_bounds__(256, 2)
k_proj_t(const float* __restrict__ x)
{
    extern __shared__ uint32_t smu[];
    uint32_t* Phs = smu;                  // [256][36]
    uint32_t* Pls = Phs + J * KP;
    uint32_t* xhs = Pls + J * KP;         // [64][36]
    uint32_t* xls = xhs + 64 * KP;
    __shared__ float diag[64];
    __shared__ float red[64][4];

    const int tid = threadIdx.x;
    const size_t row0 = (size_t)blockIdx.x * 64;
    const float* xb = x + row0 * D;

    for (int i = tid; i < J * 32; i += 256) {
        Phs[(i >> 5) * KP + (i & 31)] = g_Ph[i];
        Pls[(i >> 5) * KP + (i & 31)] = g_Pl[i];
    }
    for (int i = tid; i < 64 * 32; i += 256) {
        int r = i >> 5, c = i & 31;
        float2 f = *(const float2*)(xb + r * 64 + 2 * c);
        uint32_t hi, lo;
        split2(f.x, f.y, hi, lo);
        xhs[r * KP + c] = hi;
        xls[r * KP + c] = lo;
    }
    if (tid < 64) {
        const float4* xr = (const float4*)(xb + tid * 64);
        float s = 0.f;
#pragma unroll
        for (int i = 0; i < 16; i++) {
            float4 f = xr[i];
            s = fmaf(f.x, f.x, s); s = fmaf(f.y, f.y, s);
            s = fmaf(f.z, f.z, s); s = fmaf(f.w, f.w, s);
        }
        diag[tid] = s * DIAG_C;
    }
    __syncthreads();

    const int lane = tid & 31, wid = tid >> 5;
    const int wm = wid >> 2, wn = wid & 3;
    const int qr = lane >> 2, qc = lane & 3;

    float c[2][8][4];
#pragma unroll
    for (int mt = 0; mt < 2; mt++)
#pragma unroll
        for (int nt = 0; nt < 8; nt++)
#pragma unroll
            for (int u = 0; u < 4; u++) c[mt][nt][u] = 0.f;

#pragma unroll
    for (int ks = 0; ks < 4; ks++) {
        const int kx = ks * 8;
        uint32_t ahi[2][4], alo[2][4];
#pragma unroll
        for (int mt = 0; mt < 2; mt++) {
            int m = wm * 32 + mt * 16 + qr;
            ahi[mt][0] = xhs[m * KP + kx + qc];
            ahi[mt][1] = xhs[(m + 8) * KP + kx + qc];
            ahi[mt][2] = xhs[m * KP + kx + 4 + qc];
            ahi[mt][3] = xhs[(m + 8) * KP + kx + 4 + qc];
            alo[mt][0] = xls[m * KP + kx + qc];
            alo[mt][1] = xls[(m + 8) * KP + kx + qc];
            alo[mt][2] = xls[m * KP + kx + 4 + qc];
            alo[mt][3] = xls[(m + 8) * KP + kx + 4 + qc];
        }
#pragma unroll
        for (int nt = 0; nt < 8; nt++) {
            int j = wn * 64 + nt * 8 + qr;
            uint32_t bhi[2], blo[2];
            bhi[0] = Phs[j * KP + kx + qc];
            bhi[1] = Phs[j * KP + kx + 4 + qc];
            blo[0] = Pls[j * KP + kx + qc];
            blo[1] = Pls[j * KP + kx + 4 + qc];
#pragma unroll
            for (int mt = 0; mt < 2; mt++) {
                mma16(c[mt][nt], ahi[mt], bhi);
                mma16(c[mt][nt], alo[mt], bhi);
                mma16(c[mt][nt], ahi[mt], blo);
            }
        }
    }

    const float NEG_INF = __int_as_float(0xff800000);

    if (IS_Q) {
        float rmax[2][2];
#pragma unroll
        for (int mt = 0; mt < 2; mt++) { rmax[mt][0] = NEG_INF; rmax[mt][1] = NEG_INF; }
#pragma unroll
        for (int mt = 0; mt < 2; mt++)
#pragma unroll
            for (int nt = 0; nt < 8; nt++) {
                rmax[mt][0] = fmaxf(rmax[mt][0], fmaxf(c[mt][nt][0], c[mt][nt][1]));
                rmax[mt][1] = fmaxf(rmax[mt][1], fmaxf(c[mt][nt][2], c[mt][nt][3]));
            }
#pragma unroll
        for (int mt = 0; mt < 2; mt++)
#pragma unroll
            for (int h = 0; h < 2; h++) {
                rmax[mt][h] = fmaxf(rmax[mt][h], __shfl_xor_sync(0xffffffffu, rmax[mt][h], 1));
                rmax[mt][h] = fmaxf(rmax[mt][h], __shfl_xor_sync(0xffffffffu, rmax[mt][h], 2));
            }
        if (qc == 0) {
#pragma unroll
            for (int mt = 0; mt < 2; mt++) {
                red[wm * 32 + mt * 16 + qr][wn]     = rmax[mt][0];
                red[wm * 32 + mt * 16 + qr + 8][wn] = rmax[mt][1];
            }
        }
        __syncthreads();
        float sub[2][2];
#pragma unroll
        for (int mt = 0; mt < 2; mt++)
#pragma unroll
            for (int h = 0; h < 2; h++) {
                int row = wm * 32 + mt * 16 + qr + h * 8;
                float m4 = fmaxf(fmaxf(red[row][0], red[row][1]),
                                 fmaxf(red[row][2], red[row][3])) * DATA_NORM;
                sub[mt][h] = diag[row] + m4;
            }
#pragma unroll
        for (int mt = 0; mt < 2; mt++) {
            size_t rt = (row0 + wm * 32 + mt * 16) >> 4;
#pragma unroll
            for (int u = 0; u < 4; u++) {
                float e00 = RATIO * (fexp(fmaf(c[mt][2*u][0],   DATA_NORM, -sub[mt][0])) + KEPS);
                float e01 = RATIO * (fexp(fmaf(c[mt][2*u][1],   DATA_NORM, -sub[mt][0])) + KEPS);
                float e10 = RATIO * (fexp(fmaf(c[mt][2*u][2],   DATA_NORM, -sub[mt][1])) + KEPS);
                float e11 = RATIO * (fexp(fmaf(c[mt][2*u][3],   DATA_NORM, -sub[mt][1])) + KEPS);
                float f00 = RATIO * (fexp(fmaf(c[mt][2*u+1][0], DATA_NORM, -sub[mt][0])) + KEPS);
                float f01 = RATIO * (fexp(fmaf(c[mt][2*u+1][1], DATA_NORM, -sub[mt][0])) + KEPS);
                float f10 = RATIO * (fexp(fmaf(c[mt][2*u+1][2], DATA_NORM, -sub[mt][1])) + KEPS);
                float f11 = RATIO * (fexp(fmaf(c[mt][2*u+1][3], DATA_NORM, -sub[mt][1])) + KEPS);
                uint4 hi, lo;
                split2(e00, e01, hi.x, lo.x);
                split2(e10, e11, hi.y, lo.y);
                split2(f00, f01, hi.z, lo.z);
                split2(f10, f11, hi.w, lo.w);
                size_t t = (rt * 16 + (wn * 4 + u)) * 32 + lane;
                ((uint4*)g_qp_h)[t] = hi;
                ((uint4*)g_qp_l)[t] = lo;
            }
        }
    } else {
        float bm = NEG_INF;
#pragma unroll
        for (int mt = 0; mt < 2; mt++)
#pragma unroll
            for (int nt = 0; nt < 8; nt++)
#pragma unroll
                for (int u = 0; u < 4; u++) bm = fmaxf(bm, c[mt][nt][u]);
#pragma unroll
        for (int o = 16; o > 0; o >>= 1)
            bm = fmaxf(bm, __shfl_xor_sync(0xffffffffu, bm, o));
        if (lane == 0) red[wid][0] = bm;

        uint16_t* Eh = (uint16_t*)smu;             // [256 j][68 n] bf16
        uint16_t* El = Eh + J * 68;
        __syncthreads();
        if (tid == 0) {
            float m = red[0][0];
#pragma unroll
            for (int w = 1; w < 8; w++) m = fmaxf(m, red[w][0]);
            atomicMax(&g_kmax_u, fenc(m * DATA_NORM));
        }
#pragma unroll
        for (int mt = 0; mt < 2; mt++) {
            int r0l = wm * 32 + mt * 16 + qr;
            float d0 = diag[r0l], d1 = diag[r0l + 8];
#pragma unroll
            for (int nt = 0; nt < 8; nt++) {
                int j = wn * 64 + nt * 8 + qc * 2;
                float v00 = fexp(fmaf(c[mt][nt][0], DATA_NORM, -d0));
                float v01 = fexp(fmaf(c[mt][nt][1], DATA_NORM, -d0));
                float v10 = fexp(fmaf(c[mt][nt][2], DATA_NORM, -d1));
                float v11 = fexp(fmaf(c[mt][nt][3], DATA_NORM, -d1));
                __nv_bfloat16 h; float hf;
                h = __float2bfloat16(v00); hf = __bfloat162float(h);
                Eh[j * 68 + r0l] = *(uint16_t*)&h;
                { __nv_bfloat16 l = __float2bfloat16(v00 - hf); El[j * 68 + r0l] = *(uint16_t*)&l; }
                h = __float2bfloat16(v01); hf = __bfloat162float(h);
                Eh[(j + 1) * 68 + r0l] = *(uint16_t*)&h;
                { __nv_bfloat16 l = __float2bfloat16(v01 - hf); El[(j + 1) * 68 + r0l] = *(uint16_t*)&l; }
                h = __float2bfloat16(v10); hf = __bfloat162float(h);
                Eh[j * 68 + r0l + 8] = *(uint16_t*)&h;
                { __nv_bfloat16 l = __float2bfloat16(v10 - hf); El[j * 68 + r0l + 8] = *(uint16_t*)&l; }
                h = __float2bfloat16(v11); hf = __bfloat162float(h);
                Eh[(j + 1) * 68 + r0l + 8] = *(uint16_t*)&h;
                { __nv_bfloat16 l = __float2bfloat16(v11 - hf); El[(j + 1) * 68 + r0l + 8] = *(uint16_t*)&l; }
            }
        }
        __syncthreads();
        const int bh = (int)(row0 >> 12);
        const size_t nw0 = (row0 & 4095) >> 1;
        const uint32_t* Ehu = (const uint32_t*)Eh;
        const uint32_t* Elu = (const uint32_t*)El;
#pragma unroll
        for (int it = 0; it < 8; it++) {
            int item = it * 256 + tid;
            int tile = item >> 5, l = item & 31;
            int jt = tile >> 2, wtl = tile & 3;
            int jj = jt * 16 + (l >> 2);
            int w  = wtl * 8 + (l & 3);
            uint4 hi, lo;
            hi.x = Ehu[jj * 34 + w];        lo.x = Elu[jj * 34 + w];
            hi.y = Ehu[(jj + 8) * 34 + w];  lo.y = Elu[(jj + 8) * 34 + w];
            hi.z = Ehu[jj * 34 + w + 4];    lo.z = Elu[jj * 34 + w + 4];
            hi.w = Ehu[(jj + 8) * 34 + w+4];lo.w = Elu[(jj + 8) * 34 + w + 4];
            size_t t = (((size_t)bh * 16 + jt) * 256 + (nw0 >> 3) + wtl) * 32 + l;
            ((uint4*)g_ET_h)[t] = hi;
            ((uint4*)g_ET_l)[t] = lo;
        }
    }
}

// ===========================================================================
// Context GEMM: ctxp[j][e] = sum_n E[n][j]*vt[e][n]  (e=64 -> Esum).
// grid (BH, SPLIT); A via cp.async double-buffer, B slab (R6 form).
// smem: B 76KB + A 2x16KB = 108.8KB -> 2 CTAs/SM.
// ===========================================================================
constexpr size_t SMEM_CTX = (size_t)(2 * 72 * 132) * 4 + 2 * 1024 * 16;

__global__ void __launch_bounds__(256, 2) k_ctx_t()
{
    extern __shared__ uint32_t smu[];
    uint32_t* Bsh = smu;                         // [72][132]
    uint32_t* Bsl = Bsh + 72 * 132;
    uint4*    As4 = (uint4*)(smu + 2 * 72 * 132);  // [2][1024] (hi 512 | lo 512)
    const uint32_t As_a = smem_u32(As4);

    const int bh = blockIdx.x, s = blockIdx.y;
    const int tid = threadIdx.x, lane = tid & 31, wid = tid >> 5;
    const int qr = lane >> 2, qc = lane & 3;
    const int nwb = s * 16;

    // prologue: issue A stage 0
    {
#pragma unroll
        for (int k = 0; k < 4; k++) {
            int i = tid + k * 256;
            int jt = (i & 511) >> 5, l = i & 31;
            size_t gsrc = (((size_t)bh * 16 + jt) * 256 + nwb) * 32 + l;
            const uint4* gp = (i < 512) ? (const uint4*)g_ET_h + gsrc
                                        : (const uint4*)g_ET_l + gsrc;
            cpa16(As_a + (uint32_t)i * 16, gp);
        }
        cpa_commit();
    }
    // stage B slab (plain LDG, overlaps cp.async)
    for (int i = tid; i < 72 * 32; i += 256) {
        int e = i >> 5, w4 = i & 31;
        size_t src = ((size_t)(bh * 72 + e)) * 2048 + s * 128;
        *(float4*)(Bsh + e * 132 + w4 * 4) = ((const float4*)(g_vt_h + src))[w4];
        *(float4*)(Bsl + e * 132 + w4 * 4) = ((const float4*)(g_vt_l + src))[w4];
    }

    float c[2][9][4];
#pragma unroll
    for (int mt = 0; mt < 2; mt++)
#pragma unroll
        for (int nt = 0; nt < 9; nt++)
#pragma unroll
            for (int u = 0; u < 4; u++) c[mt][nt][u] = 0.f;

#pragma unroll 1
    for (int ck = 0; ck < 16; ck++) {
        cpa_wait0();
        __syncthreads();
        if (ck < 15) {
            int b = (ck + 1) & 1;
#pragma unroll
            for (int k = 0; k < 4; k++) {
                int i = tid + k * 256;
                int jt = (i & 511) >> 5, l = i & 31;
                size_t gsrc = (((size_t)bh * 16 + jt) * 256 + nwb + ck + 1) * 32 + l;
                const uint4* gp = (i < 512) ? (const uint4*)g_ET_h + gsrc
                                            : (const uint4*)g_ET_l + gsrc;
                cpa16(As_a + (uint32_t)(b * 1024 + i) * 16, gp);
            }
            cpa_commit();
        }
        const uint4* Ab = As4 + (ck & 1) * 1024;
        uint4 cah[2], cal[2];
#pragma unroll
        for (int mt = 0; mt < 2; mt++) {
            cah[mt] = Ab[(wid * 2 + mt) * 32 + lane];
            cal[mt] = Ab[512 + (wid * 2 + mt) * 32 + lane];
        }
        const int k0 = ck & 0;  (void)k0;
#pragma unroll
        for (int nt = 0; nt < 9; nt++) {
            int e = nt * 8 + qr;
            uint32_t bhi[2], blo[2];
            bhi[0] = Bsh[e * 132 + 8 * ck % 1 + 0 + qc];   // placeholder removed below
            bhi[0] = Bsh[e * 132 + ck * 8 + qc];
            bhi[1] = Bsh[e * 132 + ck * 8 + 4 + qc];
            blo[0] = Bsl[e * 132 + ck * 8 + qc];
            blo[1] = Bsl[e * 132 + ck * 8 + 4 + qc];
#pragma unroll
            for (int mt = 0; mt < 2; mt++) {
                mma16(c[mt][nt], (const uint32_t*)&cah[mt], bhi);
                mma16(c[mt][nt], (const uint32_t*)&cal[mt], bhi);
                mma16(c[mt][nt], (const uint32_t*)&cah[mt], blo);
            }
        }
    }

    const size_t ob = (size_t)(bh * SPLIT + s) * 256;
#pragma unroll
    for (int mt = 0; mt < 2; mt++) {
        int j = wid * 32 + mt * 16 + qr;
#pragma unroll
        for (int nt = 0; nt < 9; nt++) {
            int e = nt * 8 + qc * 2;
            *(float2*)&g_ctxp[(ob + j) * 72 + e]     = make_float2(c[mt][nt][0], c[mt][nt][1]);
            *(float2*)&g_ctxp[(ob + j + 8) * 72 + e] = make_float2(c[mt][nt][2], c[mt][nt][3]);
        }
    }
}

// ===========================================================================
// Reduce + affine + split -> bout.  grid (BH, 8): 32 j rows/block.
// ===========================================================================
__global__ void __launch_bounds__(256) k_red()
{
    __shared__ float sm[32 * 73];
    __shared__ float vsum[64];
    const int bh = blockIdx.x, g = blockIdx.y, tid = threadIdx.x;

    if (tid < 64) {
        float s = 0.f;
#pragma unroll
        for (int cg = 0; cg < 32; cg++) s += g_vsump[(bh * 32 + cg) * 64 + tid];
        vsum[tid] = s;
    }
    {
        const int jl = tid >> 3, eg = tid & 7;
        float acc[9];
#pragma unroll
        for (int u = 0; u < 9; u++) acc[u] = 0.f;
        for (int s = 0; s < SPLIT; s++) {
            const float* p = &g_ctxp[((size_t)(bh * SPLIT + s) * 256 + g * 32 + jl) * 72 + eg * 9];
#pragma unroll
            for (int u = 0; u < 9; u++) acc[u] += p[u];
        }
#pragma unroll
        for (int u = 0; u < 9; u++) sm[jl * 73 + eg * 9 + u] = acc[u];
    }
    __syncthreads();

    const float m = fdec(g_kmax_u);
    const float em = RATIO * expf(-m);
    const float epsn = RATIO * KEPS;
    for (int i = tid; i < 72 * 16; i += 256) {
        int e = i >> 4, jwl = i & 15;
        float v0 = sm[(2 * jwl) * 73 + e], v1 = sm[(2 * jwl + 1) * 73 + e];
        float a0, a1;
        if (e < 64)       { a0 = fmaf(em, v0, epsn * vsum[e]); a1 = fmaf(em, v1, epsn * vsum[e]); }
        else if (e == 64) { a0 = fmaf(em, v0, epsn * (float)N4); a1 = fmaf(em, v1, epsn * (float)N4); }
        else              { a0 = 0.f; a1 = 0.f; }
        uint32_t hi, lo;
        split2(a0, a1, hi, lo);
        g_bout_h[(bh * 72 + e) * 128 + g * 16 + jwl] = hi;
        g_bout_l[(bh * 72 + e) * 128 + g * 16 + jwl] = lo;
    }
}

// ===========================================================================
// Output GEMM: out = (qp @ [ctx^T|ksum]) / den.  1024 blocks x 128 rows.
// A via cp.async double-buffer; B slab (R6 form). smem 92.4KB -> 2 CTAs/SM.
// ===========================================================================
constexpr size_t SMEM_OUT = (size_t)(2 * 72 * 132) * 4 + 2 * 512 * 16;

__global__ void __launch_bounds__(256, 2) k_out_t(float* __restrict__ out)
{
    extern __shared__ uint32_t smu[];
    uint32_t* Bsh = smu;                         // [72][132]
    uint32_t* Bsl = Bsh + 72 * 132;
    uint4*    As4 = (uint4*)(smu + 2 * 72 * 132);  // [2][512] (hi 256 | lo 256)
    const uint32_t As_a = smem_u32(As4);

    const size_t row0 = (size_t)blockIdx.x * 128;
    const int bh = (int)(row0 >> 12);
    const int tid = threadIdx.x, lane = tid & 31, wid = tid >> 5;
    const int qr = lane >> 2, qc = lane & 3;
    const size_t rt0 = row0 >> 4;

    // prologue: issue A stage 0
    {
#pragma unroll
        for (int k = 0; k < 2; k++) {
            int i = tid + k * 256;
            int rtl = (i & 255) >> 5, l = i & 31;
            size_t gsrc = ((rt0 + rtl) * 16) * 32 + l;
            const uint4* gp = (i < 256) ? (const uint4*)g_qp_h + gsrc
                                        : (const uint4*)g_qp_l + gsrc;
            cpa16(As_a + (uint32_t)i * 16, gp);
        }
        cpa_commit();
    }
    for (int i = tid; i < 72 * 32; i += 256) {
        int e = i >> 5, w4 = i & 31;
        size_t src = (size_t)(bh * 72 + e) * 128;
        *(float4*)(Bsh + e * 132 + w4 * 4) = ((const float4*)(g_bout_h + src))[w4];
        *(float4*)(Bsl + e * 132 + w4 * 4) = ((const float4*)(g_bout_l + src))[w4];
    }

    float c[9][4];
#pragma unroll
    for (int nt = 0; nt < 9; nt++)
#pragma unroll
        for (int u = 0; u < 4; u++) c[nt][u] = 0.f;

#pragma unroll 1
    for (int ck = 0; ck < 16; ck++) {
        cpa_wait0();
        __syncthreads();
        if (ck < 15) {
            int b = (ck + 1) & 1;
#pragma unroll
            for (int k = 0; k < 2; k++) {
                int i = tid + k * 256;
                int rtl = (i & 255) >> 5, l = i & 31;
                size_t gsrc = ((rt0 + rtl) * 16 + ck + 1) * 32 + l;
                const uint4* gp = (i < 256) ? (const uint4*)g_qp_h + gsrc
                                            : (const uint4*)g_qp_l + gsrc;
                cpa16(As_a + (uint32_t)(b * 512 + i) * 16, gp);
            }
            cpa_commit();
        }
        const uint4* Ab = As4 + (ck & 1) * 512;
        uint4 cah = Ab[wid * 32 + lane];
        uint4 cal = Ab[256 + wid * 32 + lane];
        const int k0 = ck * 8;
#pragma unroll
        for (int nt = 0; nt < 9; nt++) {
            int e = nt * 8 + qr;
            uint32_t bhi[2], blo[2];
            bhi[0] = Bsh[e * 132 + k0 + qc];
            bhi[1] = Bsh[e * 132 + k0 + 4 + qc];
            blo[0] = Bsl[e * 132 + k0 + qc];
            blo[1] = Bsl[e * 132 + k0 + 4 + qc];
            mma16(c[nt], (const uint32_t*)&cah, bhi);
            mma16(c[nt], (const uint32_t*)&cal, bhi);
            mma16(c[nt], (const uint32_t*)&cah, blo);
        }
    }

    const int srcl = lane & ~3;
    float den0 = __shfl_sync(0xffffffffu, c[8][0], srcl);
    float den1 = __shfl_sync(0xffffffffu, c[8][2], srcl);
    float di0 = 1.f / den0, di1 = 1.f / den1;

    const int row = wid * 16 + qr;
#pragma unroll
    for (int nt = 0; nt < 8; nt++) {
        int e = nt * 8 + qc * 2;
        *(float2*)&out[(row0 + row) * D + e]     = make_float2(c[nt][0] * di0, c[nt][1] * di0);
        *(float2*)&out[(row0 + row + 8) * D + e] = make_float2(c[nt][2] * di1, c[nt][3] * di1);
    }
}

} // namespace fa

extern "C" void kernel_launch(void* const* d_in, const int* in_sizes, int n_in,
                              void* d_out, int out_size)
{
    using namespace fa;
    (void)in_sizes; (void)n_in; (void)out_size;

    const float* q = (const float*)d_in[0];
    const float* k = (const float*)d_in[1];
    const float* v = (const float*)d_in[2];
    const float* P = (const float*)d_in[3];
    float* out = (float*)d_out;

    cudaFuncSetAttribute(k_proj_t<true>,  cudaFuncAttributeMaxDynamicSharedMemorySize, (int)SMEM_PROJ);
    cudaFuncSetAttribute(k_proj_t<false>, cudaFuncAttributeMaxDynamicSharedMemorySize, (int)SMEM_PROJ);
    cudaFuncSetAttribute(k_ctx_t, cudaFuncAttributeMaxDynamicSharedMemorySize, (int)SMEM_CTX);
    cudaFuncSetAttribute(k_out_t, cudaFuncAttributeMaxDynamicSharedMemorySize, (int)SMEM_OUT);

    k_prep_P<<<1, 256>>>(P);
    k_prep_v<<<dim3(BH, 32), 256>>>(v);
    k_proj_t<false><<<(int)(NT / 64), 256, SMEM_PROJ>>>(k);   // E^T tiles + max
    k_ctx_t<<<dim3(BH, SPLIT), 256, SMEM_CTX>>>();            // E^T @ [v|1]
    k_proj_t<true ><<<(int)(NT / 64), 256, SMEM_PROJ>>>(q);   // qp tiles
    k_red<<<dim3(BH, 8), 256>>>();                            // affine + bout
    k_out_t<<<(int)(NT / 128), 256, SMEM_OUT>>>(out);         // qp@[ctx|ksum]/den
}

// round 11
// speedup vs baseline: 1.0905x; 1.0905x over previous
#include <cuda_runtime.h>
#include <cuda_bf16.h>
#include <math.h>
#include <stdint.h>

namespace fa {

constexpr int N4 = 4096, D = 64, J = 256, BH = 32, SPLIT = 16;
constexpr size_t NT = (size_t)BH * N4;          // 131072 rows

constexpr float DATA_NORM = 0.35355339059327373f;
constexpr float RATIO     = 0.0625f;
constexpr float DIAG_C    = 0.0625f;
constexpr float KEPS      = 1e-4f;

// ---- scratch ----
__device__ uint32_t g_Ph[J * 32], g_Pl[J * 32];       // P for q-proj (R6 path)
// P in mma-B fragment order: [jtile(32)][ks(4)][lane(32)][4: hi0,hi1,lo0,lo1]
__device__ __align__(16) uint32_t g_Pf[32 * 4 * 32 * 4];
__device__ __align__(16) uint32_t g_qp_h[NT * 128];   // qp, A-fragment-tiled
__device__ __align__(16) uint32_t g_qp_l[NT * 128];
// v^T (+ones row 64) in B-fragment order: [bh*16+s][nt(9)][ck(16)][lane][4]
__device__ __align__(16) uint32_t g_vtf[(size_t)BH * 16 * 18432];
__device__ float    g_vsump[BH * 32 * 64];
__device__ float    g_ctxp[(size_t)BH * SPLIT * 256 * 72];
__device__ __align__(16) uint32_t g_bout_h[BH * 72 * 128];
__device__ __align__(16) uint32_t g_bout_l[BH * 72 * 128];
__device__ unsigned g_kmax_u;

__device__ __forceinline__ unsigned fenc(float f) {
    unsigned u = __float_as_uint(f);
    return (u & 0x80000000u) ? ~u : (u | 0x80000000u);
}
__device__ __forceinline__ float fdec(unsigned u) {
    unsigned b = (u & 0x80000000u) ? (u & 0x7fffffffu) : ~u;
    return __uint_as_float(b);
}
__device__ __forceinline__ uint32_t bpack(float a, float b) {
    uint32_t r;
    asm("cvt.rn.bf16x2.f32 %0, %1, %2;" : "=r"(r) : "f"(b), "f"(a));
    return r;
}
__device__ __forceinline__ void split2(float a, float b, uint32_t& hi, uint32_t& lo) {
    hi = bpack(a, b);
    float ha = __uint_as_float(hi << 16);
    float hb = __uint_as_float(hi & 0xffff0000u);
    lo = bpack(a - ha, b - hb);
}
// fp32 exp via FMA-pipe poly (rel err ~1.7e-7)
__device__ __forceinline__ float fexp(float x) {
    float t = x * 1.4426950408889634f;
    float r = rintf(t);
    float f = t - r;
    float p = 1.53989857e-4f;
    p = fmaf(p, f, 1.33335581e-3f);
    p = fmaf(p, f, 9.61812910e-3f);
    p = fmaf(p, f, 5.55041087e-2f);
    p = fmaf(p, f, 2.40226507e-1f);
    p = fmaf(p, f, 6.93147181e-1f);
    p = fmaf(p, f, 1.0f);
    int ei = (int)r;
    ei = ei < -126 ? -126 : (ei > 127 ? 127 : ei);
    return p * __int_as_float((ei + 127) << 23);
}
__device__ __forceinline__ void mma16(float* c, const uint32_t* a, const uint32_t* b) {
    asm volatile(
        "mma.sync.aligned.m16n8k16.row.col.f32.bf16.bf16.f32 "
        "{%0,%1,%2,%3}, {%4,%5,%6,%7}, {%8,%9}, {%0,%1,%2,%3};"
        : "+f"(c[0]), "+f"(c[1]), "+f"(c[2]), "+f"(c[3])
        : "r"(a[0]), "r"(a[1]), "r"(a[2]), "r"(a[3]), "r"(b[0]), "r"(b[1]));
}

// ===========================================================================
// Prep P: g_Ph/g_Pl (q-proj) + g_Pf (fused, B-fragment order) + init max.
// <<<1,256>>>, thread = row j.
// ===========================================================================
__global__ void k_prep_P(const float* __restrict__ P)
{
    const int j = threadIdx.x;
    if (j == 0) g_kmax_u = 0x007FFFFFu;
    const int ntg = j >> 3, qr = j & 7;
#pragma unroll
    for (int c = 0; c < 32; c++) {
        uint32_t hi, lo;
        split2(P[j * 64 + 2 * c], P[j * 64 + 2 * c + 1], hi, lo);
        g_Ph[j * 32 + c] = hi;
        g_Pl[j * 32 + c] = lo;
        int ks = c >> 3, cc = c & 7;
        int idx = (((ntg * 4 + ks) * 32) + qr * 4 + (cc & 3)) * 4 + (cc >> 2);
        g_Pf[idx]     = hi;
        g_Pf[idx + 2] = lo;
    }
}

// ===========================================================================
// Prep v: v^T (+ones) into B-fragment order g_vtf + vsum partials.
// grid (32 bh, 32 chunks of 128 n), 256 thr.  (R8-validated layout.)
// ===========================================================================
__global__ void __launch_bounds__(256) k_prep_v(const float* __restrict__ v)
{
    __shared__ float vsm[128 * 65];
    const int bh = blockIdx.x, ch = blockIdx.y, tid = threadIdx.x;
    const size_t base = ((size_t)bh * N4 + (size_t)ch * 128) * D;
    for (int i = tid; i < 128 * 64; i += 256)
        vsm[(i >> 6) * 65 + (i & 63)] = v[base + i];
    __syncthreads();

    if (tid < 64) {
        float s = 0.f;
#pragma unroll 8
        for (int n = 0; n < 128; n++) s += vsm[n * 65 + tid];
        g_vsump[(bh * 32 + ch) * 64 + tid] = s;
    }
    const int s = ch >> 1;
    for (int i = tid; i < 72 * 64; i += 256) {
        int e = i >> 6, wwl = i & 63;
        uint32_t hi, lo;
        if (e < 64) {
            split2(vsm[(2 * wwl) * 65 + e], vsm[(2 * wwl + 1) * 65 + e], hi, lo);
        } else if (e == 64) { hi = 0x3F803F80u; lo = 0u; }
        else                { hi = 0u; lo = 0u; }
        int wl = (ch & 1) * 64 + wwl;
        int ck = wl >> 3, c = wl & 7;
        int lane = (e & 7) * 4 + (c & 3), slot = c >> 2;
        size_t idx = ((((size_t)(bh * 16 + s) * 9 + (e >> 3)) * 16 + ck) * 32 + lane) * 4 + slot;
        g_vtf[idx]     = hi;
        g_vtf[idx + 2] = lo;
    }
}

// ===========================================================================
// FUSED k-projection + context GEMM.  grid (BH, SPLIT=16), 256 thr.
// Block covers 256 n-rows of one bh, in 16 chunks of 16 rows:
//   proj chunk: dd[16][256] = (DATA_NORM*k) @ P^T  (bf16 3-split MMA, P from g_Pf)
//   E = fexp(dd*DN - diag) -> smem transpose buffer (bf16 hi/lo)
//   ctx accum:  c[j][e] += E^T(256x16) @ vtf(16x72)   (B frags from g_vtf)
// Tracks block max of dd -> atomicMax.  Stores ctxp partials (R6 layout).
// ===========================================================================
__global__ void __launch_bounds__(256, 2)
k_fused_kctx(const float* __restrict__ kx)
{
    __shared__ uint32_t xhs[16 * 36], xls[16 * 36];
    __shared__ uint16_t Eth[256 * 24], Etl[256 * 24];   // [j][n halves], u32-stride 12
    __shared__ float diag[16];
    __shared__ float wmax[8];

    const int bh = blockIdx.x, s = blockIdx.y;
    const int tid = threadIdx.x, lane = tid & 31, wid = tid >> 5;
    const int qr = lane >> 2, qc = lane & 3;
    const size_t nbase = (size_t)bh * N4 + (size_t)s * 256;

    const uint4* Pf4 = (const uint4*)g_Pf;
    const uint4* Vf4 = (const uint4*)g_vtf + (size_t)(bh * 16 + s) * 4608;

    float c[2][9][4];
#pragma unroll
    for (int mt = 0; mt < 2; mt++)
#pragma unroll
        for (int nt = 0; nt < 9; nt++)
#pragma unroll
            for (int u = 0; u < 4; u++) c[mt][nt][u] = 0.f;
    float bmax = __int_as_float(0xff800000);

#pragma unroll 1
    for (int ch = 0; ch < 16; ch++) {
        __syncthreads();   // prev chunk's ctx reads of Eth done; xhs free
        const float* xb = kx + (nbase + (size_t)ch * 16) * D;
        // stage + split x chunk (16 rows x 64)
#pragma unroll
        for (int it = 0; it < 2; it++) {
            int i = tid + it * 256;
            int r = i >> 5, cc = i & 31;
            float2 f = *(const float2*)(xb + r * 64 + 2 * cc);
            uint32_t hi, lo;
            split2(f.x, f.y, hi, lo);
            xhs[r * 36 + cc] = hi;
            xls[r * 36 + cc] = lo;
        }
        // diag: 16 threads per row, 4 elems each, shfl-reduce 16
        {
            int r = tid >> 4, sub = tid & 15;
            float4 f = ((const float4*)(xb + r * 64))[sub];
            float sl = fmaf(f.x, f.x, fmaf(f.y, f.y, fmaf(f.z, f.z, f.w * f.w)));
#pragma unroll
            for (int o = 1; o < 16; o <<= 1)
                sl += __shfl_xor_sync(0xffffffffu, sl, o);
            if (sub == 0) diag[r] = sl * DIAG_C;
        }
        __syncthreads();

        // proj MMA: warp wid covers j span wid*32 (nt 0..3)
        float cp[4][4];
#pragma unroll
        for (int nt = 0; nt < 4; nt++)
#pragma unroll
            for (int u = 0; u < 4; u++) cp[nt][u] = 0.f;
#pragma unroll
        for (int ks = 0; ks < 4; ks++) {
            const int kx8 = ks * 8;
            uint32_t ahi[4], alo[4];
            ahi[0] = xhs[qr * 36 + kx8 + qc];
            ahi[1] = xhs[(qr + 8) * 36 + kx8 + qc];
            ahi[2] = xhs[qr * 36 + kx8 + 4 + qc];
            ahi[3] = xhs[(qr + 8) * 36 + kx8 + 4 + qc];
            alo[0] = xls[qr * 36 + kx8 + qc];
            alo[1] = xls[(qr + 8) * 36 + kx8 + qc];
            alo[2] = xls[qr * 36 + kx8 + 4 + qc];
            alo[3] = xls[(qr + 8) * 36 + kx8 + 4 + qc];
#pragma unroll
            for (int nt = 0; nt < 4; nt++) {
                uint4 bf = Pf4[((wid * 4 + nt) * 4 + ks) * 32 + lane];
                uint32_t bhi[2] = {bf.x, bf.y};
                uint32_t blo[2] = {bf.z, bf.w};
                mma16(cp[nt], ahi, bhi);
                mma16(cp[nt], alo, bhi);
                mma16(cp[nt], ahi, blo);
            }
        }
        // epilogue: E = fexp(dd - diag), store transposed bf16 hi/lo; track max
        {
            float d0 = diag[qr], d1 = diag[qr + 8];
#pragma unroll
            for (int nt = 0; nt < 4; nt++) {
                bmax = fmaxf(bmax, fmaxf(fmaxf(cp[nt][0], cp[nt][1]),
                                         fmaxf(cp[nt][2], cp[nt][3])));
                int j0 = wid * 32 + nt * 8 + qc * 2;
                float v00 = fexp(fmaf(cp[nt][0], DATA_NORM, -d0));
                float v01 = fexp(fmaf(cp[nt][1], DATA_NORM, -d0));
                float v10 = fexp(fmaf(cp[nt][2], DATA_NORM, -d1));
                float v11 = fexp(fmaf(cp[nt][3], DATA_NORM, -d1));
                __nv_bfloat16 h; float hf;
                h = __float2bfloat16(v00); hf = __bfloat162float(h);
                Eth[j0 * 24 + qr] = *(uint16_t*)&h;
                { __nv_bfloat16 l = __float2bfloat16(v00 - hf); Etl[j0 * 24 + qr] = *(uint16_t*)&l; }
                h = __float2bfloat16(v01); hf = __bfloat162float(h);
                Eth[(j0 + 1) * 24 + qr] = *(uint16_t*)&h;
                { __nv_bfloat16 l = __float2bfloat16(v01 - hf); Etl[(j0 + 1) * 24 + qr] = *(uint16_t*)&l; }
                h = __float2bfloat16(v10); hf = __bfloat162float(h);
                Eth[j0 * 24 + qr + 8] = *(uint16_t*)&h;
                { __nv_bfloat16 l = __float2bfloat16(v10 - hf); Etl[j0 * 24 + qr + 8] = *(uint16_t*)&l; }
                h = __float2bfloat16(v11); hf = __bfloat162float(h);
                Eth[(j0 + 1) * 24 + qr + 8] = *(uint16_t*)&h;
                { __nv_bfloat16 l = __float2bfloat16(v11 - hf); Etl[(j0 + 1) * 24 + qr + 8] = *(uint16_t*)&l; }
            }
        }
        __syncthreads();

        // ctx accumulate: K = 16 (this chunk's n), A = Et, B = g_vtf[ck=ch]
        const uint32_t* Eh32 = (const uint32_t*)Eth;   // [j][12] u32
        const uint32_t* El32 = (const uint32_t*)Etl;
        uint32_t ahc[2][4], alc[2][4];
#pragma unroll
        for (int mt = 0; mt < 2; mt++) {
            int j = wid * 32 + mt * 16 + qr;
            ahc[mt][0] = Eh32[j * 12 + qc];
            ahc[mt][1] = Eh32[(j + 8) * 12 + qc];
            ahc[mt][2] = Eh32[j * 12 + 4 + qc];
            ahc[mt][3] = Eh32[(j + 8) * 12 + 4 + qc];
            alc[mt][0] = El32[j * 12 + qc];
            alc[mt][1] = El32[(j + 8) * 12 + qc];
            alc[mt][2] = El32[j * 12 + 4 + qc];
            alc[mt][3] = El32[(j + 8) * 12 + 4 + qc];
        }
#pragma unroll
        for (int nt = 0; nt < 9; nt++) {
            uint4 bf = Vf4[(nt * 16 + ch) * 32 + lane];
            uint32_t bhi[2] = {bf.x, bf.y};
            uint32_t blo[2] = {bf.z, bf.w};
#pragma unroll
            for (int mt = 0; mt < 2; mt++) {
                mma16(c[mt][nt], ahc[mt], bhi);
                mma16(c[mt][nt], alc[mt], bhi);
                mma16(c[mt][nt], ahc[mt], blo);
            }
        }
    }

    // block max -> global atomic
#pragma unroll
    for (int o = 16; o > 0; o >>= 1)
        bmax = fmaxf(bmax, __shfl_xor_sync(0xffffffffu, bmax, o));
    if (lane == 0) wmax[wid] = bmax;
    __syncthreads();
    if (tid == 0) {
        float m = wmax[0];
#pragma unroll
        for (int w = 1; w < 8; w++) m = fmaxf(m, wmax[w]);
        atomicMax(&g_kmax_u, fenc(m * DATA_NORM));
    }

    // store ctxp partials (R6 layout)
    const size_t ob = (size_t)(bh * SPLIT + s) * 256;
#pragma unroll
    for (int mt = 0; mt < 2; mt++) {
        int j = wid * 32 + mt * 16 + qr;
#pragma unroll
        for (int nt = 0; nt < 9; nt++) {
            int e = nt * 8 + qc * 2;
            *(float2*)&g_ctxp[(ob + j) * 72 + e]     = make_float2(c[mt][nt][0], c[mt][nt][1]);
            *(float2*)&g_ctxp[(ob + j + 8) * 72 + e] = make_float2(c[mt][nt][2], c[mt][nt][3]);
        }
    }
}

// ===========================================================================
// q-projection (R6-identical): 64 rows x 256 j per block; qp A-fragment-tiled.
// ===========================================================================
constexpr int KP = 36;
constexpr size_t SMEM_PROJ = (size_t)(2 * J * KP + 2 * 64 * KP) * sizeof(uint32_t);

__global__ void __launch_bounds__(256, 2)
k_proj_q(const float* __restrict__ x)
{
    extern __shared__ uint32_t smu[];
    uint32_t* Phs = smu;                  // [256][36]
    uint32_t* Pls = Phs + J * KP;
    uint32_t* xhs = Pls + J * KP;         // [64][36]
    uint32_t* xls = xhs + 64 * KP;
    __shared__ float diag[64];
    __shared__ float red[64][4];

    const int tid = threadIdx.x;
    const size_t row0 = (size_t)blockIdx.x * 64;
    const float* xb = x + row0 * D;

    for (int i = tid; i < J * 32; i += 256) {
        Phs[(i >> 5) * KP + (i & 31)] = g_Ph[i];
        Pls[(i >> 5) * KP + (i & 31)] = g_Pl[i];
    }
    for (int i = tid; i < 64 * 32; i += 256) {
        int r = i >> 5, c = i & 31;
        float2 f = *(const float2*)(xb + r * 64 + 2 * c);
        uint32_t hi, lo;
        split2(f.x, f.y, hi, lo);
        xhs[r * KP + c] = hi;
        xls[r * KP + c] = lo;
    }
    if (tid < 64) {
        const float4* xr = (const float4*)(xb + tid * 64);
        float s = 0.f;
#pragma unroll
        for (int i = 0; i < 16; i++) {
            float4 f = xr[i];
            s = fmaf(f.x, f.x, s); s = fmaf(f.y, f.y, s);
            s = fmaf(f.z, f.z, s); s = fmaf(f.w, f.w, s);
        }
        diag[tid] = s * DIAG_C;
    }
    __syncthreads();

    const int lane = tid & 31, wid = tid >> 5;
    const int wm = wid >> 2, wn = wid & 3;
    const int qr = lane >> 2, qc = lane & 3;

    float c[2][8][4];
#pragma unroll
    for (int mt = 0; mt < 2; mt++)
#pragma unroll
        for (int nt = 0; nt < 8; nt++)
#pragma unroll
            for (int u = 0; u < 4; u++) c[mt][nt][u] = 0.f;

#pragma unroll
    for (int ks = 0; ks < 4; ks++) {
        const int kx = ks * 8;
        uint32_t ahi[2][4], alo[2][4];
#pragma unroll
        for (int mt = 0; mt < 2; mt++) {
            int m = wm * 32 + mt * 16 + qr;
            ahi[mt][0] = xhs[m * KP + kx + qc];
            ahi[mt][1] = xhs[(m + 8) * KP + kx + qc];
            ahi[mt][2] = xhs[m * KP + kx + 4 + qc];
            ahi[mt][3] = xhs[(m + 8) * KP + kx + 4 + qc];
            alo[mt][0] = xls[m * KP + kx + qc];
            alo[mt][1] = xls[(m + 8) * KP + kx + qc];
            alo[mt][2] = xls[m * KP + kx + 4 + qc];
            alo[mt][3] = xls[(m + 8) * KP + kx + 4 + qc];
        }
#pragma unroll
        for (int nt = 0; nt < 8; nt++) {
            int j = wn * 64 + nt * 8 + qr;
            uint32_t bhi[2], blo[2];
            bhi[0] = Phs[j * KP + kx + qc];
            bhi[1] = Phs[j * KP + kx + 4 + qc];
            blo[0] = Pls[j * KP + kx + qc];
            blo[1] = Pls[j * KP + kx + 4 + qc];
#pragma unroll
            for (int mt = 0; mt < 2; mt++) {
                mma16(c[mt][nt], ahi[mt], bhi);
                mma16(c[mt][nt], alo[mt], bhi);
                mma16(c[mt][nt], ahi[mt], blo);
            }
        }
    }

    const float NEG_INF = __int_as_float(0xff800000);
    float rmax[2][2];
#pragma unroll
    for (int mt = 0; mt < 2; mt++) { rmax[mt][0] = NEG_INF; rmax[mt][1] = NEG_INF; }
#pragma unroll
    for (int mt = 0; mt < 2; mt++)
#pragma unroll
        for (int nt = 0; nt < 8; nt++) {
            rmax[mt][0] = fmaxf(rmax[mt][0], fmaxf(c[mt][nt][0], c[mt][nt][1]));
            rmax[mt][1] = fmaxf(rmax[mt][1], fmaxf(c[mt][nt][2], c[mt][nt][3]));
        }
#pragma unroll
    for (int mt = 0; mt < 2; mt++)
#pragma unroll
        for (int h = 0; h < 2; h++) {
            rmax[mt][h] = fmaxf(rmax[mt][h], __shfl_xor_sync(0xffffffffu, rmax[mt][h], 1));
            rmax[mt][h] = fmaxf(rmax[mt][h], __shfl_xor_sync(0xffffffffu, rmax[mt][h], 2));
        }
    if (qc == 0) {
#pragma unroll
        for (int mt = 0; mt < 2; mt++) {
            red[wm * 32 + mt * 16 + qr][wn]     = rmax[mt][0];
            red[wm * 32 + mt * 16 + qr + 8][wn] = rmax[mt][1];
        }
    }
    __syncthreads();
    float sub[2][2];
#pragma unroll
    for (int mt = 0; mt < 2; mt++)
#pragma unroll
        for (int h = 0; h < 2; h++) {
            int row = wm * 32 + mt * 16 + qr + h * 8;
            float m4 = fmaxf(fmaxf(red[row][0], red[row][1]),
                             fmaxf(red[row][2], red[row][3])) * DATA_NORM;
            sub[mt][h] = diag[row] + m4;
        }
#pragma unroll
    for (int mt = 0; mt < 2; mt++) {
        size_t rt = (row0 + wm * 32 + mt * 16) >> 4;
#pragma unroll
        for (int u = 0; u < 4; u++) {
            float e00 = RATIO * (fexp(fmaf(c[mt][2*u][0],   DATA_NORM, -sub[mt][0])) + KEPS);
            float e01 = RATIO * (fexp(fmaf(c[mt][2*u][1],   DATA_NORM, -sub[mt][0])) + KEPS);
            float e10 = RATIO * (fexp(fmaf(c[mt][2*u][2],   DATA_NORM, -sub[mt][1])) + KEPS);
            float e11 = RATIO * (fexp(fmaf(c[mt][2*u][3],   DATA_NORM, -sub[mt][1])) + KEPS);
            float f00 = RATIO * (fexp(fmaf(c[mt][2*u+1][0], DATA_NORM, -sub[mt][0])) + KEPS);
            float f01 = RATIO * (fexp(fmaf(c[mt][2*u+1][1], DATA_NORM, -sub[mt][0])) + KEPS);
            float f10 = RATIO * (fexp(fmaf(c[mt][2*u+1][2], DATA_NORM, -sub[mt][1])) + KEPS);
            float f11 = RATIO * (fexp(fmaf(c[mt][2*u+1][3], DATA_NORM, -sub[mt][1])) + KEPS);
            uint4 hi, lo;
            split2(e00, e01, hi.x, lo.x);
            split2(e10, e11, hi.y, lo.y);
            split2(f00, f01, hi.z, lo.z);
            split2(f10, f11, hi.w, lo.w);
            size_t t = (rt * 16 + (wn * 4 + u)) * 32 + lane;
            ((uint4*)g_qp_h)[t] = hi;
            ((uint4*)g_qp_l)[t] = lo;
        }
    }
}

// ===========================================================================
// Reduce + affine + split -> bout.  grid (BH, 8): 32 j rows/block.
// ===========================================================================
__global__ void __launch_bounds__(256) k_red()
{
    __shared__ float sm[32 * 73];
    __shared__ float vsum[64];
    const int bh = blockIdx.x, g = blockIdx.y, tid = threadIdx.x;

    if (tid < 64) {
        float s = 0.f;
#pragma unroll
        for (int cg = 0; cg < 32; cg++) s += g_vsump[(bh * 32 + cg) * 64 + tid];
        vsum[tid] = s;
    }
    {
        const int jl = tid >> 3, eg = tid & 7;
        float acc[9];
#pragma unroll
        for (int u = 0; u < 9; u++) acc[u] = 0.f;
        for (int s = 0; s < SPLIT; s++) {
            const float* p = &g_ctxp[((size_t)(bh * SPLIT + s) * 256 + g * 32 + jl) * 72 + eg * 9];
#pragma unroll
            for (int u = 0; u < 9; u++) acc[u] += p[u];
        }
#pragma unroll
        for (int u = 0; u < 9; u++) sm[jl * 73 + eg * 9 + u] = acc[u];
    }
    __syncthreads();

    const float m = fdec(g_kmax_u);
    const float em = RATIO * expf(-m);
    const float epsn = RATIO * KEPS;
    for (int i = tid; i < 72 * 16; i += 256) {
        int e = i >> 4, jwl = i & 15;
        float v0 = sm[(2 * jwl) * 73 + e], v1 = sm[(2 * jwl + 1) * 73 + e];
        float a0, a1;
        if (e < 64)       { a0 = fmaf(em, v0, epsn * vsum[e]); a1 = fmaf(em, v1, epsn * vsum[e]); }
        else if (e == 64) { a0 = fmaf(em, v0, epsn * (float)N4); a1 = fmaf(em, v1, epsn * (float)N4); }
        else              { a0 = 0.f; a1 = 0.f; }
        uint32_t hi, lo;
        split2(a0, a1, hi, lo);
        g_bout_h[(bh * 72 + e) * 128 + g * 16 + jwl] = hi;
        g_bout_l[(bh * 72 + e) * 128 + g * 16 + jwl] = lo;
    }
}

// ===========================================================================
// Output GEMM (R6-identical): out = (qp @ [ctx^T|ksum]) / den.
// ===========================================================================
constexpr size_t SMEM_OUT = (size_t)(2 * 72 * 132) * sizeof(uint32_t);

__global__ void __launch_bounds__(256, 2) k_out_t(float* __restrict__ out)
{
    extern __shared__ uint32_t smu[];
    uint32_t* Bsh = smu;              // [72][132]
    uint32_t* Bsl = Bsh + 72 * 132;

    const size_t row0 = (size_t)blockIdx.x * 128;
    const int bh = (int)(row0 >> 12);
    const int tid = threadIdx.x, lane = tid & 31, wid = tid >> 5;
    const int qr = lane >> 2, qc = lane & 3;

    for (int i = tid; i < 72 * 32; i += 256) {
        int e = i >> 5, w4 = i & 31;
        size_t src = (size_t)(bh * 72 + e) * 128;
        *(float4*)(Bsh + e * 132 + w4 * 4) = ((const float4*)(g_bout_h + src))[w4];
        *(float4*)(Bsl + e * 132 + w4 * 4) = ((const float4*)(g_bout_l + src))[w4];
    }
    __syncthreads();

    float c[9][4];
#pragma unroll
    for (int nt = 0; nt < 9; nt++)
#pragma unroll
        for (int u = 0; u < 4; u++) c[nt][u] = 0.f;

    const size_t rt = (row0 >> 4) + wid;
    const uint4* Ah4 = (const uint4*)g_qp_h + (rt * 16) * 32 + lane;
    const uint4* Al4 = (const uint4*)g_qp_l + (rt * 16) * 32 + lane;

    uint4 cah = Ah4[0], cal = Al4[0], nah, nal;
#pragma unroll 4
    for (int ck = 0; ck < 16; ck++) {
        if (ck < 15) { nah = Ah4[(ck + 1) * 32]; nal = Al4[(ck + 1) * 32]; }
        const int k0 = ck * 8;
#pragma unroll
        for (int nt = 0; nt < 9; nt++) {
            int e = nt * 8 + qr;
            uint32_t bhi[2], blo[2];
            bhi[0] = Bsh[e * 132 + k0 + qc];
            bhi[1] = Bsh[e * 132 + k0 + 4 + qc];
            blo[0] = Bsl[e * 132 + k0 + qc];
            blo[1] = Bsl[e * 132 + k0 + 4 + qc];
            mma16(c[nt], (const uint32_t*)&cah, bhi);
            mma16(c[nt], (const uint32_t*)&cal, bhi);
            mma16(c[nt], (const uint32_t*)&cah, blo);
        }
        cah = nah; cal = nal;
    }

    const int srcl = lane & ~3;
    float den0 = __shfl_sync(0xffffffffu, c[8][0], srcl);
    float den1 = __shfl_sync(0xffffffffu, c[8][2], srcl);
    float di0 = 1.f / den0, di1 = 1.f / den1;

    const int row = wid * 16 + qr;
#pragma unroll
    for (int nt = 0; nt < 8; nt++) {
        int e = nt * 8 + qc * 2;
        *(float2*)&out[(row0 + row) * D + e]     = make_float2(c[nt][0] * di0, c[nt][1] * di0);
        *(float2*)&out[(row0 + row + 8) * D + e] = make_float2(c[nt][2] * di1, c[nt][3] * di1);
    }
}

} // namespace fa

extern "C" void kernel_launch(void* const* d_in, const int* in_sizes, int n_in,
                              void* d_out, int out_size)
{
    using namespace fa;
    (void)in_sizes; (void)n_in; (void)out_size;

    const float* q = (const float*)d_in[0];
    const float* k = (const float*)d_in[1];
    const float* v = (const float*)d_in[2];
    const float* P = (const float*)d_in[3];
    float* out = (float*)d_out;

    cudaFuncSetAttribute(k_proj_q, cudaFuncAttributeMaxDynamicSharedMemorySize, (int)SMEM_PROJ);
    cudaFuncSetAttribute(k_out_t,  cudaFuncAttributeMaxDynamicSharedMemorySize, (int)SMEM_OUT);

    k_prep_P<<<1, 256>>>(P);
    k_prep_v<<<dim3(BH, 32), 256>>>(v);
    k_fused_kctx<<<dim3(BH, SPLIT), 256>>>(k);            // proj-k + exp + ctx, fused
    k_proj_q<<<(int)(NT / 64), 256, SMEM_PROJ>>>(q);      // qp tiles
    k_red<<<dim3(BH, 8), 256>>>();                        // affine + bout
    k_out_t<<<(int)(NT / 128), 256, SMEM_OUT>>>(out);     // qp@[ctx|ksum]/den
}

// round 12
// speedup vs baseline: 1.1157x; 1.0232x over previous
#include <cuda_runtime.h>
#include <cuda_bf16.h>
#include <math.h>
#include <stdint.h>

namespace fa {

constexpr int N4 = 4096, D = 64, J = 256, BH = 32, SPLIT = 16;
constexpr size_t NT = (size_t)BH * N4;          // 131072 rows

constexpr float DATA_NORM = 0.35355339059327373f;
constexpr float RATIO     = 0.0625f;
constexpr float DIAG_C    = 0.0625f;
constexpr float KEPS      = 1e-4f;

// ---- scratch ----
// P in mma-B fragment order: [jtile(32)][ks(4)][lane(32)][4: hi0,hi1,lo0,lo1]
__device__ __align__(16) uint32_t g_Pf[32 * 4 * 32 * 4];
// v^T (+ones row 64) in B-fragment order: [bh*16+s][nt(9)][ck(16)][lane][4]
__device__ __align__(16) uint32_t g_vtf[(size_t)BH * 16 * 18432];
__device__ float    g_vsump[BH * 32 * 64];
__device__ float    g_ctxp[(size_t)BH * SPLIT * 256 * 72];
__device__ __align__(16) uint32_t g_bout_h[BH * 72 * 128];
__device__ __align__(16) uint32_t g_bout_l[BH * 72 * 128];
__device__ unsigned g_kmax_u;

__device__ __forceinline__ unsigned fenc(float f) {
    unsigned u = __float_as_uint(f);
    return (u & 0x80000000u) ? ~u : (u | 0x80000000u);
}
__device__ __forceinline__ float fdec(unsigned u) {
    unsigned b = (u & 0x80000000u) ? (u & 0x7fffffffu) : ~u;
    return __uint_as_float(b);
}
__device__ __forceinline__ uint32_t bpack(float a, float b) {
    uint32_t r;
    asm("cvt.rn.bf16x2.f32 %0, %1, %2;" : "=r"(r) : "f"(b), "f"(a));
    return r;
}
__device__ __forceinline__ void split2(float a, float b, uint32_t& hi, uint32_t& lo) {
    hi = bpack(a, b);
    float ha = __uint_as_float(hi << 16);
    float hb = __uint_as_float(hi & 0xffff0000u);
    lo = bpack(a - ha, b - hb);
}
// fp32 exp via FMA-pipe poly (rel err ~1.7e-7)
__device__ __forceinline__ float fexp(float x) {
    float t = x * 1.4426950408889634f;
    float r = rintf(t);
    float f = t - r;
    float p = 1.53989857e-4f;
    p = fmaf(p, f, 1.33335581e-3f);
    p = fmaf(p, f, 9.61812910e-3f);
    p = fmaf(p, f, 5.55041087e-2f);
    p = fmaf(p, f, 2.40226507e-1f);
    p = fmaf(p, f, 6.93147181e-1f);
    p = fmaf(p, f, 1.0f);
    int ei = (int)r;
    ei = ei < -126 ? -126 : (ei > 127 ? 127 : ei);
    return p * __int_as_float((ei + 127) << 23);
}
__device__ __forceinline__ void mma16(float* c, const uint32_t* a, const uint32_t* b) {
    asm volatile(
        "mma.sync.aligned.m16n8k16.row.col.f32.bf16.bf16.f32 "
        "{%0,%1,%2,%3}, {%4,%5,%6,%7}, {%8,%9}, {%0,%1,%2,%3};"
        : "+f"(c[0]), "+f"(c[1]), "+f"(c[2]), "+f"(c[3])
        : "r"(a[0]), "r"(a[1]), "r"(a[2]), "r"(a[3]), "r"(b[0]), "r"(b[1]));
}

// ===========================================================================
// Prep P -> g_Pf (B-fragment order) + init max.  <<<1,256>>>, thread = row j.
// ===========================================================================
__global__ void k_prep_P(const float* __restrict__ P)
{
    const int j = threadIdx.x;
    if (j == 0) g_kmax_u = 0x007FFFFFu;
    const int ntg = j >> 3, qr = j & 7;
#pragma unroll
    for (int c = 0; c < 32; c++) {
        uint32_t hi, lo;
        split2(P[j * 64 + 2 * c], P[j * 64 + 2 * c + 1], hi, lo);
        int ks = c >> 3, cc = c & 7;
        int idx = (((ntg * 4 + ks) * 32) + qr * 4 + (cc & 3)) * 4 + (cc >> 2);
        g_Pf[idx]     = hi;
        g_Pf[idx + 2] = lo;
    }
}

// ===========================================================================
// Prep v: v^T (+ones) into B-fragment order g_vtf + vsum partials.
// grid (32 bh, 32 chunks of 128 n), 256 thr.
// ===========================================================================
__global__ void __launch_bounds__(256) k_prep_v(const float* __restrict__ v)
{
    __shared__ float vsm[128 * 65];
    const int bh = blockIdx.x, ch = blockIdx.y, tid = threadIdx.x;
    const size_t base = ((size_t)bh * N4 + (size_t)ch * 128) * D;
    for (int i = tid; i < 128 * 64; i += 256)
        vsm[(i >> 6) * 65 + (i & 63)] = v[base + i];
    __syncthreads();

    if (tid < 64) {
        float s = 0.f;
#pragma unroll 8
        for (int n = 0; n < 128; n++) s += vsm[n * 65 + tid];
        g_vsump[(bh * 32 + ch) * 64 + tid] = s;
    }
    const int s = ch >> 1;
    for (int i = tid; i < 72 * 64; i += 256) {
        int e = i >> 6, wwl = i & 63;
        uint32_t hi, lo;
        if (e < 64) {
            split2(vsm[(2 * wwl) * 65 + e], vsm[(2 * wwl + 1) * 65 + e], hi, lo);
        } else if (e == 64) { hi = 0x3F803F80u; lo = 0u; }
        else                { hi = 0u; lo = 0u; }
        int wl = (ch & 1) * 64 + wwl;
        int ck = wl >> 3, c = wl & 7;
        int lane = (e & 7) * 4 + (c & 3), slot = c >> 2;
        size_t idx = ((((size_t)(bh * 16 + s) * 9 + (e >> 3)) * 16 + ck) * 32 + lane) * 4 + slot;
        g_vtf[idx]     = hi;
        g_vtf[idx + 2] = lo;
    }
}

// ===========================================================================
// FUSED k-projection + context GEMM (R11-identical).  grid (BH, 16), 256 thr.
// ===========================================================================
__global__ void __launch_bounds__(256, 2)
k_fused_kctx(const float* __restrict__ kx)
{
    __shared__ uint32_t xhs[16 * 36], xls[16 * 36];
    __shared__ uint16_t Eth[256 * 24], Etl[256 * 24];   // [j][n halves], u32-stride 12
    __shared__ float diag[16];
    __shared__ float wmax[8];

    const int bh = blockIdx.x, s = blockIdx.y;
    const int tid = threadIdx.x, lane = tid & 31, wid = tid >> 5;
    const int qr = lane >> 2, qc = lane & 3;
    const size_t nbase = (size_t)bh * N4 + (size_t)s * 256;

    const uint4* Pf4 = (const uint4*)g_Pf;
    const uint4* Vf4 = (const uint4*)g_vtf + (size_t)(bh * 16 + s) * 4608;

    float c[2][9][4];
#pragma unroll
    for (int mt = 0; mt < 2; mt++)
#pragma unroll
        for (int nt = 0; nt < 9; nt++)
#pragma unroll
            for (int u = 0; u < 4; u++) c[mt][nt][u] = 0.f;
    float bmax = __int_as_float(0xff800000);

#pragma unroll 1
    for (int ch = 0; ch < 16; ch++) {
        __syncthreads();
        const float* xb = kx + (nbase + (size_t)ch * 16) * D;
#pragma unroll
        for (int it = 0; it < 2; it++) {
            int i = tid + it * 256;
            int r = i >> 5, cc = i & 31;
            float2 f = *(const float2*)(xb + r * 64 + 2 * cc);
            uint32_t hi, lo;
            split2(f.x, f.y, hi, lo);
            xhs[r * 36 + cc] = hi;
            xls[r * 36 + cc] = lo;
        }
        {
            int r = tid >> 4, sub = tid & 15;
            float4 f = ((const float4*)(xb + r * 64))[sub];
            float sl = fmaf(f.x, f.x, fmaf(f.y, f.y, fmaf(f.z, f.z, f.w * f.w)));
#pragma unroll
            for (int o = 1; o < 16; o <<= 1)
                sl += __shfl_xor_sync(0xffffffffu, sl, o);
            if (sub == 0) diag[r] = sl * DIAG_C;
        }
        __syncthreads();

        float cp[4][4];
#pragma unroll
        for (int nt = 0; nt < 4; nt++)
#pragma unroll
            for (int u = 0; u < 4; u++) cp[nt][u] = 0.f;
#pragma unroll
        for (int ks = 0; ks < 4; ks++) {
            const int kx8 = ks * 8;
            uint32_t ahi[4], alo[4];
            ahi[0] = xhs[qr * 36 + kx8 + qc];
            ahi[1] = xhs[(qr + 8) * 36 + kx8 + qc];
            ahi[2] = xhs[qr * 36 + kx8 + 4 + qc];
            ahi[3] = xhs[(qr + 8) * 36 + kx8 + 4 + qc];
            alo[0] = xls[qr * 36 + kx8 + qc];
            alo[1] = xls[(qr + 8) * 36 + kx8 + qc];
            alo[2] = xls[qr * 36 + kx8 + 4 + qc];
            alo[3] = xls[(qr + 8) * 36 + kx8 + 4 + qc];
#pragma unroll
            for (int nt = 0; nt < 4; nt++) {
                uint4 bf = Pf4[((wid * 4 + nt) * 4 + ks) * 32 + lane];
                uint32_t bhi[2] = {bf.x, bf.y};
                uint32_t blo[2] = {bf.z, bf.w};
                mma16(cp[nt], ahi, bhi);
                mma16(cp[nt], alo, bhi);
                mma16(cp[nt], ahi, blo);
            }
        }
        {
            float d0 = diag[qr], d1 = diag[qr + 8];
#pragma unroll
            for (int nt = 0; nt < 4; nt++) {
                bmax = fmaxf(bmax, fmaxf(fmaxf(cp[nt][0], cp[nt][1]),
                                         fmaxf(cp[nt][2], cp[nt][3])));
                int j0 = wid * 32 + nt * 8 + qc * 2;
                float v00 = fexp(fmaf(cp[nt][0], DATA_NORM, -d0));
                float v01 = fexp(fmaf(cp[nt][1], DATA_NORM, -d0));
                float v10 = fexp(fmaf(cp[nt][2], DATA_NORM, -d1));
                float v11 = fexp(fmaf(cp[nt][3], DATA_NORM, -d1));
                __nv_bfloat16 h; float hf;
                h = __float2bfloat16(v00); hf = __bfloat162float(h);
                Eth[j0 * 24 + qr] = *(uint16_t*)&h;
                { __nv_bfloat16 l = __float2bfloat16(v00 - hf); Etl[j0 * 24 + qr] = *(uint16_t*)&l; }
                h = __float2bfloat16(v01); hf = __bfloat162float(h);
                Eth[(j0 + 1) * 24 + qr] = *(uint16_t*)&h;
                { __nv_bfloat16 l = __float2bfloat16(v01 - hf); Etl[(j0 + 1) * 24 + qr] = *(uint16_t*)&l; }
                h = __float2bfloat16(v10); hf = __bfloat162float(h);
                Eth[j0 * 24 + qr + 8] = *(uint16_t*)&h;
                { __nv_bfloat16 l = __float2bfloat16(v10 - hf); Etl[j0 * 24 + qr + 8] = *(uint16_t*)&l; }
                h = __float2bfloat16(v11); hf = __bfloat162float(h);
                Eth[(j0 + 1) * 24 + qr + 8] = *(uint16_t*)&h;
                { __nv_bfloat16 l = __float2bfloat16(v11 - hf); Etl[(j0 + 1) * 24 + qr + 8] = *(uint16_t*)&l; }
            }
        }
        __syncthreads();

        const uint32_t* Eh32 = (const uint32_t*)Eth;
        const uint32_t* El32 = (const uint32_t*)Etl;
        uint32_t ahc[2][4], alc[2][4];
#pragma unroll
        for (int mt = 0; mt < 2; mt++) {
            int j = wid * 32 + mt * 16 + qr;
            ahc[mt][0] = Eh32[j * 12 + qc];
            ahc[mt][1] = Eh32[(j + 8) * 12 + qc];
            ahc[mt][2] = Eh32[j * 12 + 4 + qc];
            ahc[mt][3] = Eh32[(j + 8) * 12 + 4 + qc];
            alc[mt][0] = El32[j * 12 + qc];
            alc[mt][1] = El32[(j + 8) * 12 + qc];
            alc[mt][2] = El32[j * 12 + 4 + qc];
            alc[mt][3] = El32[(j + 8) * 12 + 4 + qc];
        }
#pragma unroll
        for (int nt = 0; nt < 9; nt++) {
            uint4 bf = Vf4[(nt * 16 + ch) * 32 + lane];
            uint32_t bhi[2] = {bf.x, bf.y};
            uint32_t blo[2] = {bf.z, bf.w};
#pragma unroll
            for (int mt = 0; mt < 2; mt++) {
                mma16(c[mt][nt], ahc[mt], bhi);
                mma16(c[mt][nt], alc[mt], bhi);
                mma16(c[mt][nt], ahc[mt], blo);
            }
        }
    }

#pragma unroll
    for (int o = 16; o > 0; o >>= 1)
        bmax = fmaxf(bmax, __shfl_xor_sync(0xffffffffu, bmax, o));
    if (lane == 0) wmax[wid] = bmax;
    __syncthreads();
    if (tid == 0) {
        float m = wmax[0];
#pragma unroll
        for (int w = 1; w < 8; w++) m = fmaxf(m, wmax[w]);
        atomicMax(&g_kmax_u, fenc(m * DATA_NORM));
    }

    const size_t ob = (size_t)(bh * SPLIT + s) * 256;
#pragma unroll
    for (int mt = 0; mt < 2; mt++) {
        int j = wid * 32 + mt * 16 + qr;
#pragma unroll
        for (int nt = 0; nt < 9; nt++) {
            int e = nt * 8 + qc * 2;
            *(float2*)&g_ctxp[(ob + j) * 72 + e]     = make_float2(c[mt][nt][0], c[mt][nt][1]);
            *(float2*)&g_ctxp[(ob + j + 8) * 72 + e] = make_float2(c[mt][nt][2], c[mt][nt][3]);
        }
    }
}

// ===========================================================================
// Reduce + affine + split -> bout.  grid (BH, 8): 32 j rows/block.
// ===========================================================================
__global__ void __launch_bounds__(256) k_red()
{
    __shared__ float sm[32 * 73];
    __shared__ float vsum[64];
    const int bh = blockIdx.x, g = blockIdx.y, tid = threadIdx.x;

    if (tid < 64) {
        float s = 0.f;
#pragma unroll
        for (int cg = 0; cg < 32; cg++) s += g_vsump[(bh * 32 + cg) * 64 + tid];
        vsum[tid] = s;
    }
    {
        const int jl = tid >> 3, eg = tid & 7;
        float acc[9];
#pragma unroll
        for (int u = 0; u < 9; u++) acc[u] = 0.f;
        for (int s = 0; s < SPLIT; s++) {
            const float* p = &g_ctxp[((size_t)(bh * SPLIT + s) * 256 + g * 32 + jl) * 72 + eg * 9];
#pragma unroll
            for (int u = 0; u < 9; u++) acc[u] += p[u];
        }
#pragma unroll
        for (int u = 0; u < 9; u++) sm[jl * 73 + eg * 9 + u] = acc[u];
    }
    __syncthreads();

    const float m = fdec(g_kmax_u);
    const float em = RATIO * expf(-m);
    const float epsn = RATIO * KEPS;
    for (int i = tid; i < 72 * 16; i += 256) {
        int e = i >> 4, jwl = i & 15;
        float v0 = sm[(2 * jwl) * 73 + e], v1 = sm[(2 * jwl + 1) * 73 + e];
        float a0, a1;
        if (e < 64)       { a0 = fmaf(em, v0, epsn * vsum[e]); a1 = fmaf(em, v1, epsn * vsum[e]); }
        else if (e == 64) { a0 = fmaf(em, v0, epsn * (float)N4); a1 = fmaf(em, v1, epsn * (float)N4); }
        else              { a0 = 0.f; a1 = 0.f; }
        uint32_t hi, lo;
        split2(a0, a1, hi, lo);
        g_bout_h[(bh * 72 + e) * 128 + g * 16 + jwl] = hi;
        g_bout_l[(bh * 72 + e) * 128 + g * 16 + jwl] = lo;
    }
}

// ===========================================================================
// FUSED q-projection + output GEMM.  1024 blocks x 128 rows (8 chunks of 16).
// Per chunk: proj dd[16][256] (warp = 32 j) -> rowmax (smem) -> qp frags in
// smem -> out GEMM (warp w = e tile [8w,8w+8) over all 16 j-chunks) + K-split
// denominator (warp w covers kc {2w,2w+1}, smem-reduced).
// smem (u32): Bsh[72*132] Bsl[72*132] Qh[16*132] Ql[16*132] xhs/xls[16*36].
// ===========================================================================
constexpr int QW = 132;   // Qh/Ql row stride (u32)
constexpr size_t SMEM_QOUT =
    (size_t)(2 * 72 * 132 + 2 * 16 * QW + 2 * 16 * 36) * sizeof(uint32_t);

__global__ void __launch_bounds__(256, 2)
k_fused_qout(const float* __restrict__ qx, float* __restrict__ out)
{
    extern __shared__ uint32_t smu[];
    uint32_t* Bsh = smu;                        // [72][132]
    uint32_t* Bsl = Bsh + 72 * 132;
    uint32_t* Qh  = Bsl + 72 * 132;             // [16][QW]
    uint32_t* Ql  = Qh + 16 * QW;
    uint32_t* xhs = Ql + 16 * QW;               // [16][36]
    uint32_t* xls = xhs + 16 * 36;
    __shared__ float diag[16];
    __shared__ float rmaxs[16][8];
    __shared__ float denp[8][16];

    const size_t row0 = (size_t)blockIdx.x * 128;
    const int bh = (int)(row0 >> 12);
    const int tid = threadIdx.x, lane = tid & 31, wid = tid >> 5;
    const int qr = lane >> 2, qc = lane & 3;

    const uint4* Pf4 = (const uint4*)g_Pf;

    // stage bout slab (R6 form)
    for (int i = tid; i < 72 * 32; i += 256) {
        int e = i >> 5, w4 = i & 31;
        size_t src = (size_t)(bh * 72 + e) * 128;
        *(float4*)(Bsh + e * 132 + w4 * 4) = ((const float4*)(g_bout_h + src))[w4];
        *(float4*)(Bsl + e * 132 + w4 * 4) = ((const float4*)(g_bout_l + src))[w4];
    }

#pragma unroll 1
    for (int ch = 0; ch < 8; ch++) {
        __syncthreads();   // prev chunk consumed Qh/denp; bout slab ready (ch 0)
        const float* xb = qx + (row0 + (size_t)ch * 16) * D;
        // stage + split x chunk (16 rows x 64)
#pragma unroll
        for (int it = 0; it < 2; it++) {
            int i = tid + it * 256;
            int r = i >> 5, cc = i & 31;
            float2 f = *(const float2*)(xb + r * 64 + 2 * cc);
            uint32_t hi, lo;
            split2(f.x, f.y, hi, lo);
            xhs[r * 36 + cc] = hi;
            xls[r * 36 + cc] = lo;
        }
        // diag
        {
            int r = tid >> 4, sub = tid & 15;
            float4 f = ((const float4*)(xb + r * 64))[sub];
            float sl = fmaf(f.x, f.x, fmaf(f.y, f.y, fmaf(f.z, f.z, f.w * f.w)));
#pragma unroll
            for (int o = 1; o < 16; o <<= 1)
                sl += __shfl_xor_sync(0xffffffffu, sl, o);
            if (sub == 0) diag[r] = sl * DIAG_C;
        }
        __syncthreads();

        // proj: warp wid covers j span wid*32
        float cp[4][4];
#pragma unroll
        for (int nt = 0; nt < 4; nt++)
#pragma unroll
            for (int u = 0; u < 4; u++) cp[nt][u] = 0.f;
#pragma unroll
        for (int ks = 0; ks < 4; ks++) {
            const int kx8 = ks * 8;
            uint32_t ahi[4], alo[4];
            ahi[0] = xhs[qr * 36 + kx8 + qc];
            ahi[1] = xhs[(qr + 8) * 36 + kx8 + qc];
            ahi[2] = xhs[qr * 36 + kx8 + 4 + qc];
            ahi[3] = xhs[(qr + 8) * 36 + kx8 + 4 + qc];
            alo[0] = xls[qr * 36 + kx8 + qc];
            alo[1] = xls[(qr + 8) * 36 + kx8 + qc];
            alo[2] = xls[qr * 36 + kx8 + 4 + qc];
            alo[3] = xls[(qr + 8) * 36 + kx8 + 4 + qc];
#pragma unroll
            for (int nt = 0; nt < 4; nt++) {
                uint4 bf = Pf4[((wid * 4 + nt) * 4 + ks) * 32 + lane];
                uint32_t bhi[2] = {bf.x, bf.y};
                uint32_t blo[2] = {bf.z, bf.w};
                mma16(cp[nt], ahi, bhi);
                mma16(cp[nt], alo, bhi);
                mma16(cp[nt], ahi, blo);
            }
        }

        // rowmax for this warp's j-span
        {
            float r0 = __int_as_float(0xff800000), r1 = r0;
#pragma unroll
            for (int nt = 0; nt < 4; nt++) {
                r0 = fmaxf(r0, fmaxf(cp[nt][0], cp[nt][1]));
                r1 = fmaxf(r1, fmaxf(cp[nt][2], cp[nt][3]));
            }
            r0 = fmaxf(r0, __shfl_xor_sync(0xffffffffu, r0, 1));
            r0 = fmaxf(r0, __shfl_xor_sync(0xffffffffu, r0, 2));
            r1 = fmaxf(r1, __shfl_xor_sync(0xffffffffu, r1, 1));
            r1 = fmaxf(r1, __shfl_xor_sync(0xffffffffu, r1, 2));
            if (qc == 0) { rmaxs[qr][wid] = r0; rmaxs[qr + 8][wid] = r1; }
        }
        __syncthreads();

        // qp = RATIO*(fexp(dd*DN - diag - rowmax)+eps) -> Qh/Ql fragments
        {
            float m0 = rmaxs[qr][0], m1 = rmaxs[qr + 8][0];
#pragma unroll
            for (int w = 1; w < 8; w++) {
                m0 = fmaxf(m0, rmaxs[qr][w]);
                m1 = fmaxf(m1, rmaxs[qr + 8][w]);
            }
            float sub0 = diag[qr] + m0 * DATA_NORM;
            float sub1 = diag[qr + 8] + m1 * DATA_NORM;
#pragma unroll
            for (int nt = 0; nt < 4; nt++) {
                int w = wid * 16 + nt * 4 + qc;   // word index = j0/2
                float v00 = RATIO * (fexp(fmaf(cp[nt][0], DATA_NORM, -sub0)) + KEPS);
                float v01 = RATIO * (fexp(fmaf(cp[nt][1], DATA_NORM, -sub0)) + KEPS);
                float v10 = RATIO * (fexp(fmaf(cp[nt][2], DATA_NORM, -sub1)) + KEPS);
                float v11 = RATIO * (fexp(fmaf(cp[nt][3], DATA_NORM, -sub1)) + KEPS);
                uint32_t hi, lo;
                split2(v00, v01, hi, lo);
                Qh[qr * QW + w] = hi;
                Ql[qr * QW + w] = lo;
                split2(v10, v11, hi, lo);
                Qh[(qr + 8) * QW + w] = hi;
                Ql[(qr + 8) * QW + w] = lo;
            }
        }
        __syncthreads();

        // out GEMM: warp wid owns e tile [8*wid, 8*wid+8), all 16 kc
        float co[4] = {0.f, 0.f, 0.f, 0.f};
        float cd[4] = {0.f, 0.f, 0.f, 0.f};
#pragma unroll
        for (int kc = 0; kc < 16; kc++) {
            const int k0 = kc * 8;
            uint32_t ahi[4], alo[4];
            ahi[0] = Qh[qr * QW + k0 + qc];
            ahi[1] = Qh[(qr + 8) * QW + k0 + qc];
            ahi[2] = Qh[qr * QW + k0 + 4 + qc];
            ahi[3] = Qh[(qr + 8) * QW + k0 + 4 + qc];
            alo[0] = Ql[qr * QW + k0 + qc];
            alo[1] = Ql[(qr + 8) * QW + k0 + qc];
            alo[2] = Ql[qr * QW + k0 + 4 + qc];
            alo[3] = Ql[(qr + 8) * QW + k0 + 4 + qc];
            {
                int e = wid * 8 + qr;
                uint32_t bhi[2], blo[2];
                bhi[0] = Bsh[e * 132 + k0 + qc];
                bhi[1] = Bsh[e * 132 + k0 + 4 + qc];
                blo[0] = Bsl[e * 132 + k0 + qc];
                blo[1] = Bsl[e * 132 + k0 + 4 + qc];
                mma16(co, ahi, bhi);
                mma16(co, alo, bhi);
                mma16(co, ahi, blo);
            }
            if ((kc >> 1) == wid) {   // denominator K-split: kc in {2wid, 2wid+1}
                int e = 64 + qr;
                uint32_t bhi[2], blo[2];
                bhi[0] = Bsh[e * 132 + k0 + qc];
                bhi[1] = Bsh[e * 132 + k0 + 4 + qc];
                blo[0] = Bsl[e * 132 + k0 + qc];
                blo[1] = Bsl[e * 132 + k0 + 4 + qc];
                mma16(cd, ahi, bhi);
                mma16(cd, alo, bhi);
                mma16(cd, ahi, blo);
            }
        }
        if (qc == 0) {
            denp[wid][qr]     = cd[0];
            denp[wid][qr + 8] = cd[2];
        }
        __syncthreads();
        {
            float d0 = denp[0][qr],     d1 = denp[0][qr + 8];
#pragma unroll
            for (int w = 1; w < 8; w++) { d0 += denp[w][qr]; d1 += denp[w][qr + 8]; }
            float di0 = 1.f / d0, di1 = 1.f / d1;
            size_t rb = row0 + (size_t)ch * 16;
            int e = wid * 8 + qc * 2;
            *(float2*)&out[(rb + qr) * D + e]     = make_float2(co[0] * di0, co[1] * di0);
            *(float2*)&out[(rb + qr + 8) * D + e] = make_float2(co[2] * di1, co[3] * di1);
        }
    }
}

} // namespace fa

extern "C" void kernel_launch(void* const* d_in, const int* in_sizes, int n_in,
                              void* d_out, int out_size)
{
    using namespace fa;
    (void)in_sizes; (void)n_in; (void)out_size;

    const float* q = (const float*)d_in[0];
    const float* k = (const float*)d_in[1];
    const float* v = (const float*)d_in[2];
    const float* P = (const float*)d_in[3];
    float* out = (float*)d_out;

    cudaFuncSetAttribute(k_fused_qout, cudaFuncAttributeMaxDynamicSharedMemorySize, (int)SMEM_QOUT);

    k_prep_P<<<1, 256>>>(P);
    k_prep_v<<<dim3(BH, 32), 256>>>(v);
    k_fused_kctx<<<dim3(BH, SPLIT), 256>>>(k);               // proj-k + exp + ctx
    k_red<<<dim3(BH, 8), 256>>>();                           // affine + bout
    k_fused_qout<<<(int)(NT / 128), 256, SMEM_QOUT>>>(q, out); // proj-q + out
}

// round 13
// speedup vs baseline: 1.3075x; 1.1719x over previous
#include <cuda_runtime.h>
#include <cuda_bf16.h>
#include <math.h>
#include <stdint.h>

namespace fa {

constexpr int N4 = 4096, D = 64, J = 256, BH = 32, SPLIT = 16;
constexpr size_t NT = (size_t)BH * N4;          // 131072 rows

constexpr float DATA_NORM = 0.35355339059327373f;
constexpr float RATIO     = 0.0625f;
constexpr float DIAG_C    = 0.0625f;
constexpr float KEPS      = 1e-4f;

// ---- scratch ----
// P in mma-B fragment order: [jtile(32)][ks(4)][lane(32)][4: hi0,hi1,lo0,lo1]
__device__ __align__(16) uint32_t g_Pf[32 * 4 * 32 * 4];
__device__ float    g_vsump[BH * 16 * 64];
__device__ float    g_ctxp[(size_t)BH * SPLIT * 256 * 72];
__device__ __align__(16) uint32_t g_bout_h[BH * 72 * 128];
__device__ __align__(16) uint32_t g_bout_l[BH * 72 * 128];
__device__ unsigned g_kmax_u;

__device__ __forceinline__ unsigned fenc(float f) {
    unsigned u = __float_as_uint(f);
    return (u & 0x80000000u) ? ~u : (u | 0x80000000u);
}
__device__ __forceinline__ float fdec(unsigned u) {
    unsigned b = (u & 0x80000000u) ? (u & 0x7fffffffu) : ~u;
    return __uint_as_float(b);
}
__device__ __forceinline__ uint32_t bpack(float a, float b) {
    uint32_t r;
    asm("cvt.rn.bf16x2.f32 %0, %1, %2;" : "=r"(r) : "f"(b), "f"(a));
    return r;
}
__device__ __forceinline__ void split2(float a, float b, uint32_t& hi, uint32_t& lo) {
    hi = bpack(a, b);
    float ha = __uint_as_float(hi << 16);
    float hb = __uint_as_float(hi & 0xffff0000u);
    lo = bpack(a - ha, b - hb);
}
// fp32 exp via FMA-pipe poly (rel err ~1.7e-7)
__device__ __forceinline__ float fexp(float x) {
    float t = x * 1.4426950408889634f;
    float r = rintf(t);
    float f = t - r;
    float p = 1.53989857e-4f;
    p = fmaf(p, f, 1.33335581e-3f);
    p = fmaf(p, f, 9.61812910e-3f);
    p = fmaf(p, f, 5.55041087e-2f);
    p = fmaf(p, f, 2.40226507e-1f);
    p = fmaf(p, f, 6.93147181e-1f);
    p = fmaf(p, f, 1.0f);
    int ei = (int)r;
    ei = ei < -126 ? -126 : (ei > 127 ? 127 : ei);
    return p * __int_as_float((ei + 127) << 23);
}
__device__ __forceinline__ void mma16(float* c, const uint32_t* a, const uint32_t* b) {
    asm volatile(
        "mma.sync.aligned.m16n8k16.row.col.f32.bf16.bf16.f32 "
        "{%0,%1,%2,%3}, {%4,%5,%6,%7}, {%8,%9}, {%0,%1,%2,%3};"
        : "+f"(c[0]), "+f"(c[1]), "+f"(c[2]), "+f"(c[3])
        : "r"(a[0]), "r"(a[1]), "r"(a[2]), "r"(a[3]), "r"(b[0]), "r"(b[1]));
}

// ===========================================================================
// Prep P -> g_Pf (B-fragment order) + init max.  <<<1,256>>>, thread = row j.
// ===========================================================================
__global__ void k_prep_P(const float* __restrict__ P)
{
    const int j = threadIdx.x;
    if (j == 0) g_kmax_u = 0x007FFFFFu;
    const int ntg = j >> 3, qr = j & 7;
#pragma unroll
    for (int c = 0; c < 32; c++) {
        uint32_t hi, lo;
        split2(P[j * 64 + 2 * c], P[j * 64 + 2 * c + 1], hi, lo);
        int ks = c >> 3, cc = c & 7;
        int idx = (((ntg * 4 + ks) * 32) + qr * 4 + (cc & 3)) * 4 + (cc >> 2);
        g_Pf[idx]     = hi;
        g_Pf[idx + 2] = lo;
    }
}

// ===========================================================================
// FUSED k-projection + v-transpose + context GEMM.  grid (BH, 16), 256 thr.
// Block covers 256 n-rows of one bh, in 16 chunks of 16 rows:
//   stage v[16][64] -> vsm (coalesced float4); vsum accumulate (regs)
//   transpose+split v -> Vh/Vl [72][12] B-fragment smem (rows 64..71 fixed)
//   proj chunk: dd[16][256] = k @ P^T  (bf16 3-split MMA, P from g_Pf)
//   E = fexp(dd*DN - diag) -> Eth/Etl smem transpose
//   ctx accum:  c[j][e] += E^T(256x16) @ Vh/Vl(16x72)
// Tracks block max -> atomicMax.  Stores ctxp partials + vsum partial.
// ===========================================================================
__global__ void __launch_bounds__(256, 2)
k_fused_kctx(const float* __restrict__ kx, const float* __restrict__ vx)
{
    __shared__ uint32_t xhs[16 * 36], xls[16 * 36];
    __shared__ uint16_t Eth[256 * 24], Etl[256 * 24];   // [j][n halves], u32-stride 12
    __shared__ float vsm[16 * 68];                      // v chunk [n][e]
    __shared__ uint32_t Vh[72 * 12], Vl[72 * 12];       // v^T B-fragments
    __shared__ float diag[16];
    __shared__ float wmax[8];

    const int bh = blockIdx.x, s = blockIdx.y;
    const int tid = threadIdx.x, lane = tid & 31, wid = tid >> 5;
    const int qr = lane >> 2, qc = lane & 3;
    const size_t nbase = (size_t)bh * N4 + (size_t)s * 256;

    const uint4* Pf4 = (const uint4*)g_Pf;

    // fixed B rows: e=64 -> ones, e=65..71 -> zeros
    if (tid < 96) {
        int e = 64 + tid / 12, w = tid % 12;
        Vh[e * 12 + w] = (e == 64 && w < 8) ? 0x3F803F80u : 0u;
        Vl[e * 12 + w] = 0u;
    }

    float c[2][9][4];
#pragma unroll
    for (int mt = 0; mt < 2; mt++)
#pragma unroll
        for (int nt = 0; nt < 9; nt++)
#pragma unroll
            for (int u = 0; u < 4; u++) c[mt][nt][u] = 0.f;
    float bmax = __int_as_float(0xff800000);
    float vacc = 0.f;

#pragma unroll 1
    for (int ch = 0; ch < 16; ch++) {
        __syncthreads();   // prev chunk's reads of Eth/Vh/vsm/xhs done
        const float* xb = kx + (nbase + (size_t)ch * 16) * D;
        const float* vb = vx + (nbase + (size_t)ch * 16) * D;
        // stage + split x chunk (16 rows x 64)
#pragma unroll
        for (int it = 0; it < 2; it++) {
            int i = tid + it * 256;
            int r = i >> 5, cc = i & 31;
            float2 f = *(const float2*)(xb + r * 64 + 2 * cc);
            uint32_t hi, lo;
            split2(f.x, f.y, hi, lo);
            xhs[r * 36 + cc] = hi;
            xls[r * 36 + cc] = lo;
        }
        // stage v chunk: one float4 per thread (coalesced)
        {
            int r = tid >> 4, c4 = tid & 15;
            *(float4*)(vsm + r * 68 + c4 * 4) = ((const float4*)(vb + r * 64))[c4];
        }
        // diag
        {
            int r = tid >> 4, sub = tid & 15;
            float4 f = ((const float4*)(xb + r * 64))[sub];
            float sl = fmaf(f.x, f.x, fmaf(f.y, f.y, fmaf(f.z, f.z, f.w * f.w)));
#pragma unroll
            for (int o = 1; o < 16; o <<= 1)
                sl += __shfl_xor_sync(0xffffffffu, sl, o);
            if (sub == 0) diag[r] = sl * DIAG_C;
        }
        __syncthreads();

        // vsum accumulate (64 threads)
        if (tid < 64) {
#pragma unroll
            for (int n = 0; n < 16; n++) vacc += vsm[n * 68 + tid];
        }
        // transpose + split v -> B fragments (e<64): 512 items, 2 per thread
#pragma unroll
        for (int it = 0; it < 2; it++) {
            int i = tid + it * 256;
            int e = i >> 3, w = i & 7;
            uint32_t hi, lo;
            split2(vsm[(2 * w) * 68 + e], vsm[(2 * w + 1) * 68 + e], hi, lo);
            Vh[e * 12 + w] = hi;
            Vl[e * 12 + w] = lo;
        }

        // proj MMA: warp wid covers j span wid*32 (nt 0..3)
        float cp[4][4];
#pragma unroll
        for (int nt = 0; nt < 4; nt++)
#pragma unroll
            for (int u = 0; u < 4; u++) cp[nt][u] = 0.f;
#pragma unroll
        for (int ks = 0; ks < 4; ks++) {
            const int kx8 = ks * 8;
            uint32_t ahi[4], alo[4];
            ahi[0] = xhs[qr * 36 + kx8 + qc];
            ahi[1] = xhs[(qr + 8) * 36 + kx8 + qc];
            ahi[2] = xhs[qr * 36 + kx8 + 4 + qc];
            ahi[3] = xhs[(qr + 8) * 36 + kx8 + 4 + qc];
            alo[0] = xls[qr * 36 + kx8 + qc];
            alo[1] = xls[(qr + 8) * 36 + kx8 + qc];
            alo[2] = xls[qr * 36 + kx8 + 4 + qc];
            alo[3] = xls[(qr + 8) * 36 + kx8 + 4 + qc];
#pragma unroll
            for (int nt = 0; nt < 4; nt++) {
                uint4 bf = Pf4[((wid * 4 + nt) * 4 + ks) * 32 + lane];
                uint32_t bhi[2] = {bf.x, bf.y};
                uint32_t blo[2] = {bf.z, bf.w};
                mma16(cp[nt], ahi, bhi);
                mma16(cp[nt], alo, bhi);
                mma16(cp[nt], ahi, blo);
            }
        }
        // epilogue: E = fexp(dd - diag) -> Eth/Etl; track max
        {
            float d0 = diag[qr], d1 = diag[qr + 8];
#pragma unroll
            for (int nt = 0; nt < 4; nt++) {
                bmax = fmaxf(bmax, fmaxf(fmaxf(cp[nt][0], cp[nt][1]),
                                         fmaxf(cp[nt][2], cp[nt][3])));
                int j0 = wid * 32 + nt * 8 + qc * 2;
                float v00 = fexp(fmaf(cp[nt][0], DATA_NORM, -d0));
                float v01 = fexp(fmaf(cp[nt][1], DATA_NORM, -d0));
                float v10 = fexp(fmaf(cp[nt][2], DATA_NORM, -d1));
                float v11 = fexp(fmaf(cp[nt][3], DATA_NORM, -d1));
                __nv_bfloat16 h; float hf;
                h = __float2bfloat16(v00); hf = __bfloat162float(h);
                Eth[j0 * 24 + qr] = *(uint16_t*)&h;
                { __nv_bfloat16 l = __float2bfloat16(v00 - hf); Etl[j0 * 24 + qr] = *(uint16_t*)&l; }
                h = __float2bfloat16(v01); hf = __bfloat162float(h);
                Eth[(j0 + 1) * 24 + qr] = *(uint16_t*)&h;
                { __nv_bfloat16 l = __float2bfloat16(v01 - hf); Etl[(j0 + 1) * 24 + qr] = *(uint16_t*)&l; }
                h = __float2bfloat16(v10); hf = __bfloat162float(h);
                Eth[j0 * 24 + qr + 8] = *(uint16_t*)&h;
                { __nv_bfloat16 l = __float2bfloat16(v10 - hf); Etl[j0 * 24 + qr + 8] = *(uint16_t*)&l; }
                h = __float2bfloat16(v11); hf = __bfloat162float(h);
                Eth[(j0 + 1) * 24 + qr + 8] = *(uint16_t*)&h;
                { __nv_bfloat16 l = __float2bfloat16(v11 - hf); Etl[(j0 + 1) * 24 + qr + 8] = *(uint16_t*)&l; }
            }
        }
        __syncthreads();

        // ctx accumulate: A = Eth/Etl, B = Vh/Vl
        const uint32_t* Eh32 = (const uint32_t*)Eth;
        const uint32_t* El32 = (const uint32_t*)Etl;
        uint32_t ahc[2][4], alc[2][4];
#pragma unroll
        for (int mt = 0; mt < 2; mt++) {
            int j = wid * 32 + mt * 16 + qr;
            ahc[mt][0] = Eh32[j * 12 + qc];
            ahc[mt][1] = Eh32[(j + 8) * 12 + qc];
            ahc[mt][2] = Eh32[j * 12 + 4 + qc];
            ahc[mt][3] = Eh32[(j + 8) * 12 + 4 + qc];
            alc[mt][0] = El32[j * 12 + qc];
            alc[mt][1] = El32[(j + 8) * 12 + qc];
            alc[mt][2] = El32[j * 12 + 4 + qc];
            alc[mt][3] = El32[(j + 8) * 12 + 4 + qc];
        }
#pragma unroll
        for (int nt = 0; nt < 9; nt++) {
            int e = nt * 8 + qr;
            uint32_t bhi[2], blo[2];
            bhi[0] = Vh[e * 12 + qc];
            bhi[1] = Vh[e * 12 + 4 + qc];
            blo[0] = Vl[e * 12 + qc];
            blo[1] = Vl[e * 12 + 4 + qc];
#pragma unroll
            for (int mt = 0; mt < 2; mt++) {
                mma16(c[mt][nt], ahc[mt], bhi);
                mma16(c[mt][nt], alc[mt], bhi);
                mma16(c[mt][nt], ahc[mt], blo);
            }
        }
    }

    // block max -> global atomic
#pragma unroll
    for (int o = 16; o > 0; o >>= 1)
        bmax = fmaxf(bmax, __shfl_xor_sync(0xffffffffu, bmax, o));
    if (lane == 0) wmax[wid] = bmax;
    __syncthreads();
    if (tid == 0) {
        float m = wmax[0];
#pragma unroll
        for (int w = 1; w < 8; w++) m = fmaxf(m, wmax[w]);
        atomicMax(&g_kmax_u, fenc(m * DATA_NORM));
    }
    // vsum partial
    if (tid < 64) g_vsump[(bh * 16 + s) * 64 + tid] = vacc;

    // store ctxp partials
    const size_t ob = (size_t)(bh * SPLIT + s) * 256;
#pragma unroll
    for (int mt = 0; mt < 2; mt++) {
        int j = wid * 32 + mt * 16 + qr;
#pragma unroll
        for (int nt = 0; nt < 9; nt++) {
            int e = nt * 8 + qc * 2;
            *(float2*)&g_ctxp[(ob + j) * 72 + e]     = make_float2(c[mt][nt][0], c[mt][nt][1]);
            *(float2*)&g_ctxp[(ob + j + 8) * 72 + e] = make_float2(c[mt][nt][2], c[mt][nt][3]);
        }
    }
}

// ===========================================================================
// Reduce + affine + split -> bout.  grid (BH, 8): 32 j rows/block.
// ===========================================================================
__global__ void __launch_bounds__(256) k_red()
{
    __shared__ float sm[32 * 73];
    __shared__ float vsum[64];
    const int bh = blockIdx.x, g = blockIdx.y, tid = threadIdx.x;

    if (tid < 64) {
        float s = 0.f;
#pragma unroll
        for (int cg = 0; cg < 16; cg++) s += g_vsump[(bh * 16 + cg) * 64 + tid];
        vsum[tid] = s;
    }
    {
        const int jl = tid >> 3, eg = tid & 7;
        float acc[9];
#pragma unroll
        for (int u = 0; u < 9; u++) acc[u] = 0.f;
        for (int s = 0; s < SPLIT; s++) {
            const float* p = &g_ctxp[((size_t)(bh * SPLIT + s) * 256 + g * 32 + jl) * 72 + eg * 9];
#pragma unroll
            for (int u = 0; u < 9; u++) acc[u] += p[u];
        }
#pragma unroll
        for (int u = 0; u < 9; u++) sm[jl * 73 + eg * 9 + u] = acc[u];
    }
    __syncthreads();

    const float m = fdec(g_kmax_u);
    const float em = RATIO * expf(-m);
    const float epsn = RATIO * KEPS;
    for (int i = tid; i < 72 * 16; i += 256) {
        int e = i >> 4, jwl = i & 15;
        float v0 = sm[(2 * jwl) * 73 + e], v1 = sm[(2 * jwl + 1) * 73 + e];
        float a0, a1;
        if (e < 64)       { a0 = fmaf(em, v0, epsn * vsum[e]); a1 = fmaf(em, v1, epsn * vsum[e]); }
        else if (e == 64) { a0 = fmaf(em, v0, epsn * (float)N4); a1 = fmaf(em, v1, epsn * (float)N4); }
        else              { a0 = 0.f; a1 = 0.f; }
        uint32_t hi, lo;
        split2(a0, a1, hi, lo);
        g_bout_h[(bh * 72 + e) * 128 + g * 16 + jwl] = hi;
        g_bout_l[(bh * 72 + e) * 128 + g * 16 + jwl] = lo;
    }
}

// ===========================================================================
// FUSED q-projection + output GEMM (R12-identical).  1024 blocks x 128 rows.
// ===========================================================================
constexpr int QW = 132;   // Qh/Ql row stride (u32)
constexpr size_t SMEM_QOUT =
    (size_t)(2 * 72 * 132 + 2 * 16 * QW + 2 * 16 * 36) * sizeof(uint32_t);

__global__ void __launch_bounds__(256, 2)
k_fused_qout(const float* __restrict__ qx, float* __restrict__ out)
{
    extern __shared__ uint32_t smu[];
    uint32_t* Bsh = smu;                        // [72][132]
    uint32_t* Bsl = Bsh + 72 * 132;
    uint32_t* Qh  = Bsl + 72 * 132;             // [16][QW]
    uint32_t* Ql  = Qh + 16 * QW;
    uint32_t* xhs = Ql + 16 * QW;               // [16][36]
    uint32_t* xls = xhs + 16 * 36;
    __shared__ float diag[16];
    __shared__ float rmaxs[16][8];
    __shared__ float denp[8][16];

    const size_t row0 = (size_t)blockIdx.x * 128;
    const int bh = (int)(row0 >> 12);
    const int tid = threadIdx.x, lane = tid & 31, wid = tid >> 5;
    const int qr = lane >> 2, qc = lane & 3;

    const uint4* Pf4 = (const uint4*)g_Pf;

    for (int i = tid; i < 72 * 32; i += 256) {
        int e = i >> 5, w4 = i & 31;
        size_t src = (size_t)(bh * 72 + e) * 128;
        *(float4*)(Bsh + e * 132 + w4 * 4) = ((const float4*)(g_bout_h + src))[w4];
        *(float4*)(Bsl + e * 132 + w4 * 4) = ((const float4*)(g_bout_l + src))[w4];
    }

#pragma unroll 1
    for (int ch = 0; ch < 8; ch++) {
        __syncthreads();
        const float* xb = qx + (row0 + (size_t)ch * 16) * D;
#pragma unroll
        for (int it = 0; it < 2; it++) {
            int i = tid + it * 256;
            int r = i >> 5, cc = i & 31;
            float2 f = *(const float2*)(xb + r * 64 + 2 * cc);
            uint32_t hi, lo;
            split2(f.x, f.y, hi, lo);
            xhs[r * 36 + cc] = hi;
            xls[r * 36 + cc] = lo;
        }
        {
            int r = tid >> 4, sub = tid & 15;
            float4 f = ((const float4*)(xb + r * 64))[sub];
            float sl = fmaf(f.x, f.x, fmaf(f.y, f.y, fmaf(f.z, f.z, f.w * f.w)));
#pragma unroll
            for (int o = 1; o < 16; o <<= 1)
                sl += __shfl_xor_sync(0xffffffffu, sl, o);
            if (sub == 0) diag[r] = sl * DIAG_C;
        }
        __syncthreads();

        float cp[4][4];
#pragma unroll
        for (int nt = 0; nt < 4; nt++)
#pragma unroll
            for (int u = 0; u < 4; u++) cp[nt][u] = 0.f;
#pragma unroll
        for (int ks = 0; ks < 4; ks++) {
            const int kx8 = ks * 8;
            uint32_t ahi[4], alo[4];
            ahi[0] = xhs[qr * 36 + kx8 + qc];
            ahi[1] = xhs[(qr + 8) * 36 + kx8 + qc];
            ahi[2] = xhs[qr * 36 + kx8 + 4 + qc];
            ahi[3] = xhs[(qr + 8) * 36 + kx8 + 4 + qc];
            alo[0] = xls[qr * 36 + kx8 + qc];
            alo[1] = xls[(qr + 8) * 36 + kx8 + qc];
            alo[2] = xls[qr * 36 + kx8 + 4 + qc];
            alo[3] = xls[(qr + 8) * 36 + kx8 + 4 + qc];
#pragma unroll
            for (int nt = 0; nt < 4; nt++) {
                uint4 bf = Pf4[((wid * 4 + nt) * 4 + ks) * 32 + lane];
                uint32_t bhi[2] = {bf.x, bf.y};
                uint32_t blo[2] = {bf.z, bf.w};
                mma16(cp[nt], ahi, bhi);
                mma16(cp[nt], alo, bhi);
                mma16(cp[nt], ahi, blo);
            }
        }

        {
            float r0 = __int_as_float(0xff800000), r1 = r0;
#pragma unroll
            for (int nt = 0; nt < 4; nt++) {
                r0 = fmaxf(r0, fmaxf(cp[nt][0], cp[nt][1]));
                r1 = fmaxf(r1, fmaxf(cp[nt][2], cp[nt][3]));
            }
            r0 = fmaxf(r0, __shfl_xor_sync(0xffffffffu, r0, 1));
            r0 = fmaxf(r0, __shfl_xor_sync(0xffffffffu, r0, 2));
            r1 = fmaxf(r1, __shfl_xor_sync(0xffffffffu, r1, 1));
            r1 = fmaxf(r1, __shfl_xor_sync(0xffffffffu, r1, 2));
            if (qc == 0) { rmaxs[qr][wid] = r0; rmaxs[qr + 8][wid] = r1; }
        }
        __syncthreads();

        {
            float m0 = rmaxs[qr][0], m1 = rmaxs[qr + 8][0];
#pragma unroll
            for (int w = 1; w < 8; w++) {
                m0 = fmaxf(m0, rmaxs[qr][w]);
                m1 = fmaxf(m1, rmaxs[qr + 8][w]);
            }
            float sub0 = diag[qr] + m0 * DATA_NORM;
            float sub1 = diag[qr + 8] + m1 * DATA_NORM;
#pragma unroll
            for (int nt = 0; nt < 4; nt++) {
                int w = wid * 16 + nt * 4 + qc;
                float v00 = RATIO * (fexp(fmaf(cp[nt][0], DATA_NORM, -sub0)) + KEPS);
                float v01 = RATIO * (fexp(fmaf(cp[nt][1], DATA_NORM, -sub0)) + KEPS);
                float v10 = RATIO * (fexp(fmaf(cp[nt][2], DATA_NORM, -sub1)) + KEPS);
                float v11 = RATIO * (fexp(fmaf(cp[nt][3], DATA_NORM, -sub1)) + KEPS);
                uint32_t hi, lo;
                split2(v00, v01, hi, lo);
                Qh[qr * QW + w] = hi;
                Ql[qr * QW + w] = lo;
                split2(v10, v11, hi, lo);
                Qh[(qr + 8) * QW + w] = hi;
                Ql[(qr + 8) * QW + w] = lo;
            }
        }
        __syncthreads();

        float co[4] = {0.f, 0.f, 0.f, 0.f};
        float cd[4] = {0.f, 0.f, 0.f, 0.f};
#pragma unroll
        for (int kc = 0; kc < 16; kc++) {
            const int k0 = kc * 8;
            uint32_t ahi[4], alo[4];
            ahi[0] = Qh[qr * QW + k0 + qc];
            ahi[1] = Qh[(qr + 8) * QW + k0 + qc];
            ahi[2] = Qh[qr * QW + k0 + 4 + qc];
            ahi[3] = Qh[(qr + 8) * QW + k0 + 4 + qc];
            alo[0] = Ql[qr * QW + k0 + qc];
            alo[1] = Ql[(qr + 8) * QW + k0 + qc];
            alo[2] = Ql[qr * QW + k0 + 4 + qc];
            alo[3] = Ql[(qr + 8) * QW + k0 + 4 + qc];
            {
                int e = wid * 8 + qr;
                uint32_t bhi[2], blo[2];
                bhi[0] = Bsh[e * 132 + k0 + qc];
                bhi[1] = Bsh[e * 132 + k0 + 4 + qc];
                blo[0] = Bsl[e * 132 + k0 + qc];
                blo[1] = Bsl[e * 132 + k0 + 4 + qc];
                mma16(co, ahi, bhi);
                mma16(co, alo, bhi);
                mma16(co, ahi, blo);
            }
            if ((kc >> 1) == wid) {
                int e = 64 + qr;
                uint32_t bhi[2], blo[2];
                bhi[0] = Bsh[e * 132 + k0 + qc];
                bhi[1] = Bsh[e * 132 + k0 + 4 + qc];
                blo[0] = Bsl[e * 132 + k0 + qc];
                blo[1] = Bsl[e * 132 + k0 + 4 + qc];
                mma16(cd, ahi, bhi);
                mma16(cd, alo, bhi);
                mma16(cd, ahi, blo);
            }
        }
        if (qc == 0) {
            denp[wid][qr]     = cd[0];
            denp[wid][qr + 8] = cd[2];
        }
        __syncthreads();
        {
            float d0 = denp[0][qr],     d1 = denp[0][qr + 8];
#pragma unroll
            for (int w = 1; w < 8; w++) { d0 += denp[w][qr]; d1 += denp[w][qr + 8]; }
            float di0 = 1.f / d0, di1 = 1.f / d1;
            size_t rb = row0 + (size_t)ch * 16;
            int e = wid * 8 + qc * 2;
            *(float2*)&out[(rb + qr) * D + e]     = make_float2(co[0] * di0, co[1] * di0);
            *(float2*)&out[(rb + qr + 8) * D + e] = make_float2(co[2] * di1, co[3] * di1);
        }
    }
}

} // namespace fa

extern "C" void kernel_launch(void* const* d_in, const int* in_sizes, int n_in,
                              void* d_out, int out_size)
{
    using namespace fa;
    (void)in_sizes; (void)n_in; (void)out_size;

    const float* q = (const float*)d_in[0];
    const float* k = (const float*)d_in[1];
    const float* v = (const float*)d_in[2];
    const float* P = (const float*)d_in[3];
    float* out = (float*)d_out;

    cudaFuncSetAttribute(k_fused_qout, cudaFuncAttributeMaxDynamicSharedMemorySize, (int)SMEM_QOUT);

    k_prep_P<<<1, 256>>>(P);
    k_fused_kctx<<<dim3(BH, SPLIT), 256>>>(k, v);            // proj-k + v^T + ctx
    k_red<<<dim3(BH, 8), 256>>>();                           // affine + bout
    k_fused_qout<<<(int)(NT / 128), 256, SMEM_QOUT>>>(q, out); // proj-q + out
}